// round 1
// baseline (speedup 1.0000x reference)
#include <cuda_runtime.h>

#define NN 50000
#define EE 1600000
#define RR 7
#define DD 128
#define GG 64
#define NS (NN*RR)      // 350000 segments
#define KK 1024         // R*D + D (fused A width)
#define NLAYERS 3
#define GSPLIT 16

// ---------------- scratch (device globals; no allocation allowed) ----------
__device__ float g_A[(size_t)NN*KK];     // 204.8 MB: [upd(896) | x(128)] per node
__device__ float g_x[(size_t)NN*DD];     // 25.6 MB current features
__device__ int   g_cnt[NS];
__device__ int   g_start[NS+1];
__device__ int   g_cur[NS];
__device__ int   g_esrc[EE];
__device__ float g_ew[EE];
__device__ float g_W[KK*DD];             // concatenated [W_rel; W_loop] for a layer
__device__ float g_bias[DD];
__device__ int   g_bsum[512];

// ---------------- CSR build ------------------------------------------------
__global__ void k_zero_cnt(){
    int i = blockIdx.x*blockDim.x + threadIdx.x;
    if (i < NS) g_cnt[i] = 0;
}

__global__ void k_hist(const int* __restrict__ nout, const int* __restrict__ rel){
    int e = blockIdx.x*blockDim.x + threadIdx.x;
    if (e < EE) atomicAdd(&g_cnt[nout[e]*RR + rel[e]], 1);
}

__global__ void k_scan1(){
    __shared__ int sm[1024];
    int t = threadIdx.x;
    int i = blockIdx.x*1024 + t;
    int v = (i < NS) ? g_cnt[i] : 0;
    sm[t] = v; __syncthreads();
    for (int off = 1; off < 1024; off <<= 1){
        int u = (t >= off) ? sm[t-off] : 0;
        __syncthreads();
        sm[t] += u;
        __syncthreads();
    }
    if (i < NS) g_start[i] = sm[t] - v;      // exclusive within block
    if (t == 1023) g_bsum[blockIdx.x] = sm[t];
}

__global__ void k_scan2(int nb){
    __shared__ int sm[512];
    int t = threadIdx.x;
    int v = (t < nb) ? g_bsum[t] : 0;
    sm[t] = v; __syncthreads();
    for (int off = 1; off < 512; off <<= 1){
        int u = (t >= off) ? sm[t-off] : 0;
        __syncthreads();
        sm[t] += u;
        __syncthreads();
    }
    if (t < nb) g_bsum[t] = sm[t] - v;       // exclusive block offsets
}

__global__ void k_scan3(){
    int t = threadIdx.x;
    int i = blockIdx.x*1024 + t;
    if (i < NS){
        int s = g_start[i] + g_bsum[blockIdx.x];
        g_start[i] = s;
        g_cur[i]   = s;
    }
    if (i == 0) g_start[NS] = EE;
}

__global__ void k_scatter(const int* __restrict__ nin, const int* __restrict__ nout,
                          const int* __restrict__ rel, const float* __restrict__ ewt){
    int e = blockIdx.x*blockDim.x + threadIdx.x;
    if (e < EE){
        int s = nout[e]*RR + rel[e];
        int p = atomicAdd(&g_cur[s], 1);
        g_esrc[p] = nin[e];
        g_ew[p]   = ewt[e];
    }
}

// ---------------- embedding / x copy --------------------------------------
__global__ void k_embed(const int* __restrict__ ut, const float4* __restrict__ emb4){
    int i = blockIdx.x*blockDim.x + threadIdx.x;
    if (i < NN*32){
        int n = i >> 5, q = i & 31;
        ((float4*)g_x)[i] = emb4[ut[n]*32 + q];
    }
}

__global__ void k_copyx(){
    int i = blockIdx.x*blockDim.x + threadIdx.x;
    if (i < NN*32){
        int n = i >> 5, q = i & 31;
        ((float4*)g_A)[n*256 + 224 + q] = ((const float4*)g_x)[i];
    }
}

// ---------------- per-layer aggregate: warp per segment -------------------
__global__ void k_agg(){
    int w = (blockIdx.x*blockDim.x + threadIdx.x) >> 5;
    int lane = threadIdx.x & 31;
    if (w >= NS) return;
    int beg = g_start[w], end = g_start[w+1];
    const float4* x4 = (const float4*)g_x;
    float4 acc = make_float4(0.f, 0.f, 0.f, 0.f);
    for (int j = beg; j < end; j++){
        int   src = g_esrc[j];
        float wt  = g_ew[j];
        float4 v  = __ldg(&x4[src*32 + lane]);
        acc.x += wt*v.x; acc.y += wt*v.y; acc.z += wt*v.z; acc.w += wt*v.w;
    }
    int n = w / RR, r = w - n*RR;
    ((float4*)g_A)[n*256 + r*32 + lane] = acc;
}

// ---------------- weight concat prep --------------------------------------
__global__ void k_prepW(const float* __restrict__ Wrel, const float* __restrict__ brel,
                        const float* __restrict__ Wloop, const float* __restrict__ bloop,
                        int layer){
    int i = blockIdx.x*blockDim.x + threadIdx.x;
    if (i < KK*DD){
        int k = i >> 7, j = i & 127;
        if (k < 896)
            g_W[i] = Wrel[(size_t)layer*896*128 + i];
        else
            g_W[i] = Wloop[(size_t)layer*128*128 + (k-896)*128 + j];
    }
    if (i < DD) g_bias[i] = brel[layer*DD + i] + bloop[layer*DD + i];
}

// ---------------- fused GEMM + bias + relu: C[M,128] = A[M,1024] * W ------
__global__ void __launch_bounds__(256, 2) k_gemm(float* __restrict__ out, int M){
    __shared__ float As[16*132];   // padded rows to reduce STS conflicts
    __shared__ float Bs[16*128];
    int tid = threadIdx.x, tx = tid & 15, ty = tid >> 4;
    int m0 = blockIdx.x * 128;

    float acc[8][8];
    #pragma unroll
    for (int i = 0; i < 8; i++)
        #pragma unroll
        for (int j = 0; j < 8; j++) acc[i][j] = 0.f;

    for (int kt = 0; kt < KK; kt += 16){
        #pragma unroll
        for (int i = 0; i < 2; i++){
            int idx = tid + i*256;
            int r = idx >> 2, q = idx & 3;
            int m = m0 + r;
            float4 v = (m < M) ? *(const float4*)(g_A + (size_t)m*KK + kt + q*4)
                               : make_float4(0.f,0.f,0.f,0.f);
            As[(q*4+0)*132 + r] = v.x;
            As[(q*4+1)*132 + r] = v.y;
            As[(q*4+2)*132 + r] = v.z;
            As[(q*4+3)*132 + r] = v.w;
        }
        #pragma unroll
        for (int i = 0; i < 2; i++){
            int idx = tid + i*256;
            int r = idx >> 5, q = idx & 31;
            *(float4*)&Bs[r*128 + q*4] = *(const float4*)(g_W + (kt + r)*128 + q*4);
        }
        __syncthreads();
        #pragma unroll
        for (int k = 0; k < 16; k++){
            float a[8], b[8];
            *(float4*)(a)   = *(float4*)&As[k*132 + ty*4];
            *(float4*)(a+4) = *(float4*)&As[k*132 + 64 + ty*4];
            *(float4*)(b)   = *(float4*)&Bs[k*128 + tx*4];
            *(float4*)(b+4) = *(float4*)&Bs[k*128 + 64 + tx*4];
            #pragma unroll
            for (int i = 0; i < 8; i++)
                #pragma unroll
                for (int j = 0; j < 8; j++)
                    acc[i][j] += a[i]*b[j];
        }
        __syncthreads();
    }

    float bb[8];
    *(float4*)(bb)   = *(const float4*)&g_bias[tx*4];
    *(float4*)(bb+4) = *(const float4*)&g_bias[64 + tx*4];

    #pragma unroll
    for (int i = 0; i < 8; i++){
        int m = m0 + ((i < 4) ? (ty*4 + i) : (64 + ty*4 + i - 4));
        if (m < M){
            float4 o1, o2;
            o1.x = fmaxf(acc[i][0] + bb[0], 0.f);
            o1.y = fmaxf(acc[i][1] + bb[1], 0.f);
            o1.z = fmaxf(acc[i][2] + bb[2], 0.f);
            o1.w = fmaxf(acc[i][3] + bb[3], 0.f);
            o2.x = fmaxf(acc[i][4] + bb[4], 0.f);
            o2.y = fmaxf(acc[i][5] + bb[5], 0.f);
            o2.z = fmaxf(acc[i][6] + bb[6], 0.f);
            o2.w = fmaxf(acc[i][7] + bb[7], 0.f);
            *(float4*)(out + (size_t)m*128 + tx*4)      = o1;
            *(float4*)(out + (size_t)m*128 + 64 + tx*4) = o2;
        }
    }
}

// gemm writing into internal g_x (next-layer input)
__global__ void __launch_bounds__(256, 2) k_gemm_to_gx(int M);

// Simple wrapper trick: reuse one kernel body with a destination flag.
__global__ void __launch_bounds__(256, 2) k_gemm_gx(int M){
    // identical body but writes g_x; implemented by calling pattern below
    // (duplicated body for simplicity)
    __shared__ float As[16*132];
    __shared__ float Bs[16*128];
    int tid = threadIdx.x, tx = tid & 15, ty = tid >> 4;
    int m0 = blockIdx.x * 128;
    float acc[8][8];
    #pragma unroll
    for (int i = 0; i < 8; i++)
        #pragma unroll
        for (int j = 0; j < 8; j++) acc[i][j] = 0.f;
    for (int kt = 0; kt < KK; kt += 16){
        #pragma unroll
        for (int i = 0; i < 2; i++){
            int idx = tid + i*256;
            int r = idx >> 2, q = idx & 3;
            int m = m0 + r;
            float4 v = (m < M) ? *(const float4*)(g_A + (size_t)m*KK + kt + q*4)
                               : make_float4(0.f,0.f,0.f,0.f);
            As[(q*4+0)*132 + r] = v.x;
            As[(q*4+1)*132 + r] = v.y;
            As[(q*4+2)*132 + r] = v.z;
            As[(q*4+3)*132 + r] = v.w;
        }
        #pragma unroll
        for (int i = 0; i < 2; i++){
            int idx = tid + i*256;
            int r = idx >> 5, q = idx & 31;
            *(float4*)&Bs[r*128 + q*4] = *(const float4*)(g_W + (kt + r)*128 + q*4);
        }
        __syncthreads();
        #pragma unroll
        for (int k = 0; k < 16; k++){
            float a[8], b[8];
            *(float4*)(a)   = *(float4*)&As[k*132 + ty*4];
            *(float4*)(a+4) = *(float4*)&As[k*132 + 64 + ty*4];
            *(float4*)(b)   = *(float4*)&Bs[k*128 + tx*4];
            *(float4*)(b+4) = *(float4*)&Bs[k*128 + 64 + tx*4];
            #pragma unroll
            for (int i = 0; i < 8; i++)
                #pragma unroll
                for (int j = 0; j < 8; j++)
                    acc[i][j] += a[i]*b[j];
        }
        __syncthreads();
    }
    float bb[8];
    *(float4*)(bb)   = *(const float4*)&g_bias[tx*4];
    *(float4*)(bb+4) = *(const float4*)&g_bias[64 + tx*4];
    #pragma unroll
    for (int i = 0; i < 8; i++){
        int m = m0 + ((i < 4) ? (ty*4 + i) : (64 + ty*4 + i - 4));
        if (m < M){
            float4 o1, o2;
            o1.x = fmaxf(acc[i][0] + bb[0], 0.f);
            o1.y = fmaxf(acc[i][1] + bb[1], 0.f);
            o1.z = fmaxf(acc[i][2] + bb[2], 0.f);
            o1.w = fmaxf(acc[i][3] + bb[3], 0.f);
            o2.x = fmaxf(acc[i][4] + bb[4], 0.f);
            o2.y = fmaxf(acc[i][5] + bb[5], 0.f);
            o2.z = fmaxf(acc[i][6] + bb[6], 0.f);
            o2.w = fmaxf(acc[i][7] + bb[7], 0.f);
            *(float4*)(g_x + (size_t)m*128 + tx*4)      = o1;
            *(float4*)(g_x + (size_t)m*128 + 64 + tx*4) = o2;
        }
    }
}

// ---------------- graph pooling -------------------------------------------
__global__ void k_zero_out(float* __restrict__ out){
    int i = blockIdx.x*blockDim.x + threadIdx.x;
    if (i < GG*DD) out[i] = 0.f;
}

__device__ __forceinline__ int lowerb(const int* __restrict__ a, int n, int key){
    int lo = 0, hi = n;
    while (lo < hi){
        int mid = (lo + hi) >> 1;
        if (a[mid] < key) lo = mid + 1; else hi = mid;
    }
    return lo;
}

__global__ void k_gsum(const int* __restrict__ n2g, const float* __restrict__ x,
                       float* __restrict__ out){
    int g = blockIdx.x / GSPLIT, c = blockIdx.x % GSPLIT, t = threadIdx.x;
    int lo = lowerb(n2g, NN, g);
    int hi = lowerb(n2g, NN, g+1);
    int len = hi - lo;
    int per = (len + GSPLIT - 1) / GSPLIT;
    int s = lo + c*per;
    int e = min(s + per, hi);
    float acc = 0.f;
    for (int n = s; n < e; n++) acc += x[(size_t)n*DD + t];
    if (e > s) atomicAdd(&out[g*DD + t], acc);
}

// ---------------- launcher -------------------------------------------------
extern "C" void kernel_launch(void* const* d_in, const int* in_sizes, int n_in,
                              void* d_out, int out_size){
    const int*   unit_type   = (const int*)  d_in[0];
    const int*   node_in     = (const int*)  d_in[1];
    const int*   node_out    = (const int*)  d_in[2];
    const int*   relation    = (const int*)  d_in[3];
    const float* edge_weight = (const float*)d_in[4];
    const int*   node2graph  = (const int*)  d_in[5];
    const float* emb         = (const float*)d_in[6];
    const float* W_rel       = (const float*)d_in[7];
    const float* b_rel       = (const float*)d_in[8];
    const float* W_loop      = (const float*)d_in[9];
    const float* b_loop      = (const float*)d_in[10];

    float* out   = (float*)d_out;
    float* x_out = out + GG*DD;

    int nb_ns = (NS + 1023) / 1024;  // 342

    // CSR build (seg is layer-invariant; rebuilt every call — deterministic work)
    k_zero_cnt<<<nb_ns, 1024>>>();
    k_hist<<<(EE + 255)/256, 256>>>(node_out, relation);
    k_scan1<<<nb_ns, 1024>>>();
    k_scan2<<<1, 512>>>(nb_ns);
    k_scan3<<<nb_ns, 1024>>>();
    k_scatter<<<(EE + 255)/256, 256>>>(node_in, node_out, relation, edge_weight);

    k_embed<<<(NN*32 + 255)/256, 256>>>(unit_type, (const float4*)emb);

    for (int l = 0; l < NLAYERS; l++){
        k_copyx<<<(NN*32 + 255)/256, 256>>>();
        k_agg<<<(NS*32 + 255)/256, 256>>>();
        k_prepW<<<(KK*DD + 255)/256, 256>>>(W_rel, b_rel, W_loop, b_loop, l);
        if (l < NLAYERS - 1)
            k_gemm_gx<<<(NN + 127)/128, 256>>>(NN);
        else
            k_gemm<<<(NN + 127)/128, 256>>>(x_out, NN);
    }

    k_zero_out<<<(GG*DD + 255)/256, 256>>>(out);
    k_gsum<<<GG*GSPLIT, 128>>>(node2graph, x_out, out);
}

// round 5
// speedup vs baseline: 1.7452x; 1.7452x over previous
#include <cuda_runtime.h>
#include <cuda_bf16.h>
#include <cstdint>

#define NN 50000
#define NPAD 50048          // 391 * 128
#define EE 1600000
#define RR 7
#define DD 128
#define GG 64
#define NS (NN*RR)
#define KK 1024             // R*D + D
#define NLAYERS 3
#define GSPLIT 16
#define NCHUNK 16           // K chunks of 64
#define MTILES (NPAD/128)   // 391
#define GEMM_SMEM 65536

// ---------------- scratch (device globals; zero-initialized at load) -------
__device__ __align__(16) __nv_bfloat16 g_Ah[(size_t)NPAD*KK]; // hi part of A
__device__ __align__(16) __nv_bfloat16 g_Al[(size_t)NPAD*KK]; // lo part of A
__device__ __align__(16) float g_x[(size_t)NN*DD];
__device__ __align__(16) __nv_bfloat16 g_Bh[DD*KK];  // Wt hi [n][k] (k contiguous)
__device__ __align__(16) __nv_bfloat16 g_Bl[DD*KK];  // Wt lo
__device__ __align__(16) float g_bias[DD];
__device__ int   g_cnt[NS];
__device__ int   g_start[NS+1];
__device__ int   g_cur[NS];
__device__ int   g_esrc[EE];
__device__ float g_ew[EE];
__device__ int   g_bsum[512];

// ---------------- helpers ---------------------------------------------------
__device__ __forceinline__ uint32_t smem_u32(const void* p){
    uint32_t a;
    asm("{ .reg .u64 t; cvta.to.shared.u64 t, %1; cvt.u32.u64 %0, t; }" : "=r"(a) : "l"(p));
    return a;
}
#define SMEM_SWIZZLE_128B(o) ((o) ^ (((o) >> 3) & 0x70))

__device__ __forceinline__ void ldsm4(uint32_t* r, uint32_t addr){
    asm volatile("ldmatrix.sync.aligned.m8n8.x4.shared.b16 {%0,%1,%2,%3}, [%4];"
        : "=r"(r[0]), "=r"(r[1]), "=r"(r[2]), "=r"(r[3]) : "r"(addr));
}
__device__ __forceinline__ void mma16816(float* c, const uint32_t* a, const uint32_t* b){
    asm volatile("mma.sync.aligned.m16n8k16.row.col.f32.bf16.bf16.f32 "
        "{%0,%1,%2,%3}, {%4,%5,%6,%7}, {%8,%9}, {%0,%1,%2,%3};"
        : "+f"(c[0]), "+f"(c[1]), "+f"(c[2]), "+f"(c[3])
        : "r"(a[0]), "r"(a[1]), "r"(a[2]), "r"(a[3]), "r"(b[0]), "r"(b[1]));
}

// ---------------- split helpers --------------------------------------------
__device__ __forceinline__ void split_store4(__nv_bfloat16* Ah, __nv_bfloat16* Al,
                                             size_t off, float4 v){
    __nv_bfloat162 h01, h23, l01, l23;
    h01.x = __float2bfloat16(v.x); h01.y = __float2bfloat16(v.y);
    h23.x = __float2bfloat16(v.z); h23.y = __float2bfloat16(v.w);
    l01.x = __float2bfloat16(v.x - __bfloat162float(h01.x));
    l01.y = __float2bfloat16(v.y - __bfloat162float(h01.y));
    l23.x = __float2bfloat16(v.z - __bfloat162float(h23.x));
    l23.y = __float2bfloat16(v.w - __bfloat162float(h23.y));
    *reinterpret_cast<__nv_bfloat162*>(Ah + off)     = h01;
    *reinterpret_cast<__nv_bfloat162*>(Ah + off + 2) = h23;
    *reinterpret_cast<__nv_bfloat162*>(Al + off)     = l01;
    *reinterpret_cast<__nv_bfloat162*>(Al + off + 2) = l23;
}
__device__ __forceinline__ void split_store2(size_t off, float a, float b){
    __nv_bfloat162 h, l;
    h.x = __float2bfloat16(a); h.y = __float2bfloat16(b);
    l.x = __float2bfloat16(a - __bfloat162float(h.x));
    l.y = __float2bfloat16(b - __bfloat162float(h.y));
    *reinterpret_cast<__nv_bfloat162*>(g_Ah + off) = h;
    *reinterpret_cast<__nv_bfloat162*>(g_Al + off) = l;
}

// ---------------- CSR build ------------------------------------------------
__global__ void k_zero_cnt(){
    int i = blockIdx.x*blockDim.x + threadIdx.x;
    if (i < NS) g_cnt[i] = 0;
}
__global__ void k_hist(const int* __restrict__ nout, const int* __restrict__ rel){
    int e = blockIdx.x*blockDim.x + threadIdx.x;
    if (e < EE) atomicAdd(&g_cnt[nout[e]*RR + rel[e]], 1);
}
__global__ void k_scan1(){
    __shared__ int sm[1024];
    int t = threadIdx.x;
    int i = blockIdx.x*1024 + t;
    int v = (i < NS) ? g_cnt[i] : 0;
    sm[t] = v; __syncthreads();
    for (int off = 1; off < 1024; off <<= 1){
        int u = (t >= off) ? sm[t-off] : 0;
        __syncthreads();
        sm[t] += u;
        __syncthreads();
    }
    if (i < NS) g_start[i] = sm[t] - v;
    if (t == 1023) g_bsum[blockIdx.x] = sm[t];
}
__global__ void k_scan2(int nb){
    __shared__ int sm[512];
    int t = threadIdx.x;
    int v = (t < nb) ? g_bsum[t] : 0;
    sm[t] = v; __syncthreads();
    for (int off = 1; off < 512; off <<= 1){
        int u = (t >= off) ? sm[t-off] : 0;
        __syncthreads();
        sm[t] += u;
        __syncthreads();
    }
    if (t < nb) g_bsum[t] = sm[t] - v;
}
__global__ void k_scan3(){
    int t = threadIdx.x;
    int i = blockIdx.x*1024 + t;
    if (i < NS){
        int s = g_start[i] + g_bsum[blockIdx.x];
        g_start[i] = s;
        g_cur[i]   = s;
    }
    if (i == 0) g_start[NS] = EE;
}
__global__ void k_scatter(const int* __restrict__ nin, const int* __restrict__ nout,
                          const int* __restrict__ rel, const float* __restrict__ ewt){
    int e = blockIdx.x*blockDim.x + threadIdx.x;
    if (e < EE){
        int s = nout[e]*RR + rel[e];
        int p = atomicAdd(&g_cur[s], 1);
        g_esrc[p] = nin[e];
        g_ew[p]   = ewt[e];
    }
}

// ---------------- embedding (writes g_x + split x into A cols 896..1023) ---
__global__ void k_embed(const int* __restrict__ ut, const float4* __restrict__ emb4){
    int i = blockIdx.x*blockDim.x + threadIdx.x;
    if (i < NN*32){
        int n = i >> 5, q = i & 31;
        float4 v = emb4[ut[n]*32 + q];
        ((float4*)g_x)[i] = v;
        split_store4(g_Ah, g_Al, (size_t)n*KK + 896 + q*4, v);
    }
}

// ---------------- per-layer aggregate: warp per segment --------------------
__global__ void k_agg(){
    int w = (blockIdx.x*blockDim.x + threadIdx.x) >> 5;
    int lane = threadIdx.x & 31;
    if (w >= NS) return;
    int beg = g_start[w], end = g_start[w+1];
    const float4* x4 = (const float4*)g_x;
    float4 acc = make_float4(0.f, 0.f, 0.f, 0.f);
    for (int j = beg; j < end; j++){
        int   src = g_esrc[j];
        float wt  = g_ew[j];
        float4 v  = __ldg(&x4[src*32 + lane]);
        acc.x += wt*v.x; acc.y += wt*v.y; acc.z += wt*v.z; acc.w += wt*v.w;
    }
    int n = w / RR, r = w - n*RR;
    split_store4(g_Ah, g_Al, (size_t)n*KK + r*DD + lane*4, acc);
}

// ---------------- weight transpose + split ---------------------------------
__global__ void k_prepW(const float* __restrict__ Wrel, const float* __restrict__ brel,
                        const float* __restrict__ Wloop, const float* __restrict__ bloop,
                        int layer){
    int i = blockIdx.x*blockDim.x + threadIdx.x;
    if (i < KK*DD){
        int n = i >> 10, k = i & 1023;
        float v = (k < 896)
            ? Wrel [(size_t)layer*896*128 + (size_t)k*128 + n]
            : Wloop[(size_t)layer*128*128 + (size_t)(k-896)*128 + n];
        __nv_bfloat16 h = __float2bfloat16(v);
        g_Bh[i] = h;
        g_Bl[i] = __float2bfloat16(v - __bfloat162float(h));
    }
    if (i < DD) g_bias[i] = brel[layer*DD + i] + bloop[layer*DD + i];
}

// ---------------- mma.sync GEMM: C[128tile,128] = A[.,1024] * Wt^T ---------
// split-3: Ah*Bh + Al*Bh + Ah*Bl, fp32 accum in registers.
// smem: 4 tiles of 128 rows x 64 bf16 (128B rows, xor-swizzled), 16KB each.
__global__ void __launch_bounds__(256, 2) k_gemm_mma(float* __restrict__ xout, int writeAux){
    extern __shared__ char dsm[];
    char* pAH = dsm;
    char* pAL = dsm + 16384;
    char* pBH = dsm + 32768;
    char* pBL = dsm + 49152;
    uint32_t sAH = smem_u32(pAH);
    uint32_t sAL = sAH + 16384;
    uint32_t sBH = sAH + 32768;
    uint32_t sBL = sAH + 49152;

    int tid  = threadIdx.x;
    int wid  = tid >> 5;
    int lane = tid & 31;
    int wm   = wid & 3;      // 4 warps along M
    int wn   = wid >> 2;     // 2 warps along N
    int m0   = blockIdx.x * 128;

    // per-lane UN-swizzled row/col components; swizzle applied per K-step
    uint32_t a_rowb = (uint32_t)(((lane & 7) + ((lane >> 3) & 1) * 8 + wm * 32) * 128);
    uint32_t a_kb   = ((lane >> 4) & 1) * 16;
    uint32_t b_rowb = (uint32_t)(((lane & 7) + ((lane >> 4) & 1) * 8 + wn * 64) * 128);
    uint32_t b_kb   = ((lane >> 3) & 1) * 16;

    float acc[2][8][4];
    #pragma unroll
    for (int mt = 0; mt < 2; mt++)
        #pragma unroll
        for (int nt = 0; nt < 8; nt++)
            #pragma unroll
            for (int q = 0; q < 4; q++) acc[mt][nt][q] = 0.f;

    const char* srcs[4] = {
        (const char*)g_Ah + (size_t)m0*2048,
        (const char*)g_Al + (size_t)m0*2048,
        (const char*)g_Bh,
        (const char*)g_Bl };
    char* dsts[4] = { pAH, pAL, pBH, pBL };

    for (int kc = 0; kc < NCHUNK; kc++){
        size_t kbyte = (size_t)kc * 128;
        #pragma unroll
        for (int t4 = 0; t4 < 4; t4++){
            #pragma unroll
            for (int i = 0; i < 4; i++){
                int idx = tid + i*256;
                int row = idx >> 3;
                int seg = (idx & 7) * 16;
                uint4 v = *(const uint4*)(srcs[t4] + (size_t)row*2048 + kbyte + seg);
                *(uint4*)(dsts[t4] + SMEM_SWIZZLE_128B(row*128 + seg)) = v;
            }
        }
        __syncthreads();

        #pragma unroll
        for (int ks = 0; ks < 4; ks++){
            uint32_t koff = ks * 32;
            // exact swizzle on the full un-swizzled offset (kb+koff <= 112, carry-free);
            // +mt*2048 / +np*2048 add 16 rows: row bits [2:0] unchanged -> swizzle-invariant
            uint32_t a_off = SMEM_SWIZZLE_128B(a_rowb + a_kb + koff);
            uint32_t b_off = SMEM_SWIZZLE_128B(b_rowb + b_kb + koff);
            uint32_t ah[2][4], al[2][4];
            #pragma unroll
            for (int mt = 0; mt < 2; mt++){
                ldsm4(ah[mt], sAH + a_off + mt*2048);
                ldsm4(al[mt], sAL + a_off + mt*2048);
            }
            #pragma unroll
            for (int np = 0; np < 4; np++){
                uint32_t bh[4], bl[4];
                ldsm4(bh, sBH + b_off + np*2048);
                ldsm4(bl, sBL + b_off + np*2048);
                #pragma unroll
                for (int half = 0; half < 2; half++){
                    int nt = np*2 + half;
                    #pragma unroll
                    for (int mt = 0; mt < 2; mt++){
                        mma16816(acc[mt][nt], ah[mt], bh + half*2);
                        mma16816(acc[mt][nt], al[mt], bh + half*2);
                        mma16816(acc[mt][nt], ah[mt], bl + half*2);
                    }
                }
            }
        }
        __syncthreads();
    }

    // epilogue: bias + relu, write out (and optionally g_x + split into A aux cols)
    int qrow = lane >> 2;            // 0..7
    int qcol = (lane & 3) * 2;       // 0,2,4,6
    #pragma unroll
    for (int mt = 0; mt < 2; mt++){
        #pragma unroll
        for (int nt = 0; nt < 8; nt++){
            int col  = wn*64 + nt*8 + qcol;
            float2 bb = *(const float2*)&g_bias[col];
            int r0 = m0 + wm*32 + mt*16 + qrow;
            int r1 = r0 + 8;
            float v00 = fmaxf(acc[mt][nt][0] + bb.x, 0.f);
            float v01 = fmaxf(acc[mt][nt][1] + bb.y, 0.f);
            float v10 = fmaxf(acc[mt][nt][2] + bb.x, 0.f);
            float v11 = fmaxf(acc[mt][nt][3] + bb.y, 0.f);
            if (writeAux){
                if (r0 < NN){
                    *(float2*)&g_x[(size_t)r0*DD + col] = make_float2(v00, v01);
                    split_store2((size_t)r0*KK + 896 + col, v00, v01);
                }
                if (r1 < NN){
                    *(float2*)&g_x[(size_t)r1*DD + col] = make_float2(v10, v11);
                    split_store2((size_t)r1*KK + 896 + col, v10, v11);
                }
            } else {
                if (r0 < NN) *(float2*)&xout[(size_t)r0*DD + col] = make_float2(v00, v01);
                if (r1 < NN) *(float2*)&xout[(size_t)r1*DD + col] = make_float2(v10, v11);
            }
        }
    }
}

// ---------------- graph pooling --------------------------------------------
__global__ void k_zero_out(float* __restrict__ out){
    int i = blockIdx.x*blockDim.x + threadIdx.x;
    if (i < GG*DD) out[i] = 0.f;
}
__device__ __forceinline__ int lowerb(const int* __restrict__ a, int n, int key){
    int lo = 0, hi = n;
    while (lo < hi){
        int mid = (lo + hi) >> 1;
        if (a[mid] < key) lo = mid + 1; else hi = mid;
    }
    return lo;
}
__global__ void k_gsum(const int* __restrict__ n2g, const float* __restrict__ x,
                       float* __restrict__ out){
    int g = blockIdx.x / GSPLIT, c = blockIdx.x % GSPLIT, t = threadIdx.x;
    int lo = lowerb(n2g, NN, g);
    int hi = lowerb(n2g, NN, g+1);
    int len = hi - lo;
    int per = (len + GSPLIT - 1) / GSPLIT;
    int s = lo + c*per;
    int e = min(s + per, hi);
    float acc = 0.f;
    for (int n = s; n < e; n++) acc += x[(size_t)n*DD + t];
    if (e > s) atomicAdd(&out[g*DD + t], acc);
}

// ---------------- launcher --------------------------------------------------
extern "C" void kernel_launch(void* const* d_in, const int* in_sizes, int n_in,
                              void* d_out, int out_size){
    const int*   unit_type   = (const int*)  d_in[0];
    const int*   node_in     = (const int*)  d_in[1];
    const int*   node_out    = (const int*)  d_in[2];
    const int*   relation    = (const int*)  d_in[3];
    const float* edge_weight = (const float*)d_in[4];
    const int*   node2graph  = (const int*)  d_in[5];
    const float* emb         = (const float*)d_in[6];
    const float* W_rel       = (const float*)d_in[7];
    const float* b_rel       = (const float*)d_in[8];
    const float* W_loop      = (const float*)d_in[9];
    const float* b_loop      = (const float*)d_in[10];

    float* out   = (float*)d_out;
    float* x_out = out + GG*DD;

    // idempotent, capture-safe; no static guard (harness rule)
    cudaFuncSetAttribute(k_gemm_mma, cudaFuncAttributeMaxDynamicSharedMemorySize, GEMM_SMEM);

    int nb_ns = (NS + 1023) / 1024;  // 342

    k_zero_cnt<<<nb_ns, 1024>>>();
    k_hist<<<(EE + 255)/256, 256>>>(node_out, relation);
    k_scan1<<<nb_ns, 1024>>>();
    k_scan2<<<1, 512>>>(nb_ns);
    k_scan3<<<nb_ns, 1024>>>();
    k_scatter<<<(EE + 255)/256, 256>>>(node_in, node_out, relation, edge_weight);

    k_embed<<<(NN*32 + 255)/256, 256>>>(unit_type, (const float4*)emb);

    for (int l = 0; l < NLAYERS; l++){
        k_agg<<<(NS*32 + 255)/256, 256>>>();
        k_prepW<<<(KK*DD + 255)/256, 256>>>(W_rel, b_rel, W_loop, b_loop, l);
        if (l < NLAYERS - 1)
            k_gemm_mma<<<MTILES, 256, GEMM_SMEM>>>(nullptr, 1);
        else
            k_gemm_mma<<<MTILES, 256, GEMM_SMEM>>>(x_out, 0);
    }

    k_zero_out<<<(GG*DD + 255)/256, 256>>>(out);
    k_gsum<<<GG*GSPLIT, 128>>>(node2graph, x_out, out);
}

// round 6
// speedup vs baseline: 1.7666x; 1.0122x over previous
#include <cuda_runtime.h>
#include <cuda_bf16.h>
#include <cstdint>

#define NN 50000
#define NPAD 50048          // 391 * 128
#define EE 1600000
#define RR 7
#define DD 128
#define GG 64
#define NS (NN*RR)
#define KK 1024             // R*D + D
#define NLAYERS 3
#define GSPLIT 16
#define NCHUNK 16           // K chunks of 64
#define MTILES (NPAD/128)   // 391
#define STAGE_BYTES 65536
#define GEMM_SMEM (2*STAGE_BYTES)

// ---------------- scratch (device globals; zero-initialized at load) -------
__device__ __align__(16) __nv_bfloat16 g_Ah[(size_t)NPAD*KK]; // hi part of A
__device__ __align__(16) __nv_bfloat16 g_Al[(size_t)NPAD*KK]; // lo part of A
__device__ __align__(16) float g_x[(size_t)NN*DD];
__device__ __align__(16) __nv_bfloat16 g_Bh3[NLAYERS][DD*KK]; // Wt hi [n][k]
__device__ __align__(16) __nv_bfloat16 g_Bl3[NLAYERS][DD*KK]; // Wt lo
__device__ __align__(16) float g_bias3[NLAYERS][DD];
__device__ int   g_cnt[NS];
__device__ int   g_start[NS+1];
__device__ int   g_cur[NS];
__device__ __align__(8) int2 g_edge[EE];   // (src, ew bits)
__device__ int   g_bsum[512];

// ---------------- helpers ---------------------------------------------------
__device__ __forceinline__ uint32_t smem_u32(const void* p){
    uint32_t a;
    asm("{ .reg .u64 t; cvta.to.shared.u64 t, %1; cvt.u32.u64 %0, t; }" : "=r"(a) : "l"(p));
    return a;
}
#define SMEM_SWIZZLE_128B(o) ((o) ^ (((o) >> 3) & 0x70))

#define CP_ASYNC16(dst, src) \
    asm volatile("cp.async.cg.shared.global [%0], [%1], 16;" :: "r"(dst), "l"(src))
#define CP_COMMIT() asm volatile("cp.async.commit_group;" ::: "memory")
#define CP_WAIT1()  asm volatile("cp.async.wait_group 1;" ::: "memory")
#define CP_WAIT0()  asm volatile("cp.async.wait_group 0;" ::: "memory")

__device__ __forceinline__ void ldsm4(uint32_t* r, uint32_t addr){
    asm volatile("ldmatrix.sync.aligned.m8n8.x4.shared.b16 {%0,%1,%2,%3}, [%4];"
        : "=r"(r[0]), "=r"(r[1]), "=r"(r[2]), "=r"(r[3]) : "r"(addr));
}
__device__ __forceinline__ void mma16816(float* c, const uint32_t* a, const uint32_t* b){
    asm volatile("mma.sync.aligned.m16n8k16.row.col.f32.bf16.bf16.f32 "
        "{%0,%1,%2,%3}, {%4,%5,%6,%7}, {%8,%9}, {%0,%1,%2,%3};"
        : "+f"(c[0]), "+f"(c[1]), "+f"(c[2]), "+f"(c[3])
        : "r"(a[0]), "r"(a[1]), "r"(a[2]), "r"(a[3]), "r"(b[0]), "r"(b[1]));
}

// ---------------- split helpers --------------------------------------------
__device__ __forceinline__ void split_store4(__nv_bfloat16* Ah, __nv_bfloat16* Al,
                                             size_t off, float4 v){
    __nv_bfloat162 h01, h23, l01, l23;
    h01.x = __float2bfloat16(v.x); h01.y = __float2bfloat16(v.y);
    h23.x = __float2bfloat16(v.z); h23.y = __float2bfloat16(v.w);
    l01.x = __float2bfloat16(v.x - __bfloat162float(h01.x));
    l01.y = __float2bfloat16(v.y - __bfloat162float(h01.y));
    l23.x = __float2bfloat16(v.z - __bfloat162float(h23.x));
    l23.y = __float2bfloat16(v.w - __bfloat162float(h23.y));
    *reinterpret_cast<__nv_bfloat162*>(Ah + off)     = h01;
    *reinterpret_cast<__nv_bfloat162*>(Ah + off + 2) = h23;
    *reinterpret_cast<__nv_bfloat162*>(Al + off)     = l01;
    *reinterpret_cast<__nv_bfloat162*>(Al + off + 2) = l23;
}
__device__ __forceinline__ void split_store2(size_t off, float a, float b){
    __nv_bfloat162 h, l;
    h.x = __float2bfloat16(a); h.y = __float2bfloat16(b);
    l.x = __float2bfloat16(a - __bfloat162float(h.x));
    l.y = __float2bfloat16(b - __bfloat162float(h.y));
    *reinterpret_cast<__nv_bfloat162*>(g_Ah + off) = h;
    *reinterpret_cast<__nv_bfloat162*>(g_Al + off) = l;
}

// ---------------- CSR build ------------------------------------------------
__global__ void k_zero_cnt(){
    int i = blockIdx.x*blockDim.x + threadIdx.x;
    if (i < NS) g_cnt[i] = 0;
}
__global__ void k_hist(const int* __restrict__ nout, const int* __restrict__ rel){
    int e = blockIdx.x*blockDim.x + threadIdx.x;
    if (e < EE) atomicAdd(&g_cnt[nout[e]*RR + rel[e]], 1);
}
__global__ void k_scan1(){
    __shared__ int sm[1024];
    int t = threadIdx.x;
    int i = blockIdx.x*1024 + t;
    int v = (i < NS) ? g_cnt[i] : 0;
    sm[t] = v; __syncthreads();
    for (int off = 1; off < 1024; off <<= 1){
        int u = (t >= off) ? sm[t-off] : 0;
        __syncthreads();
        sm[t] += u;
        __syncthreads();
    }
    if (i < NS) g_start[i] = sm[t] - v;
    if (t == 1023) g_bsum[blockIdx.x] = sm[t];
}
__global__ void k_scan2(int nb){
    __shared__ int sm[512];
    int t = threadIdx.x;
    int v = (t < nb) ? g_bsum[t] : 0;
    sm[t] = v; __syncthreads();
    for (int off = 1; off < 512; off <<= 1){
        int u = (t >= off) ? sm[t-off] : 0;
        __syncthreads();
        sm[t] += u;
        __syncthreads();
    }
    if (t < nb) g_bsum[t] = sm[t] - v;
}
__global__ void k_scan3(){
    int t = threadIdx.x;
    int i = blockIdx.x*1024 + t;
    if (i < NS){
        int s = g_start[i] + g_bsum[blockIdx.x];
        g_start[i] = s;
        g_cur[i]   = s;
    }
    if (i == 0) g_start[NS] = EE;
}
__global__ void k_scatter(const int* __restrict__ nin, const int* __restrict__ nout,
                          const int* __restrict__ rel, const float* __restrict__ ewt){
    int e = blockIdx.x*blockDim.x + threadIdx.x;
    if (e < EE){
        int s = nout[e]*RR + rel[e];
        int p = atomicAdd(&g_cur[s], 1);
        g_edge[p] = make_int2(nin[e], __float_as_int(ewt[e]));
    }
}

// ---------------- embedding (writes g_x + split x into A cols 896..1023) ---
__global__ void k_embed(const int* __restrict__ ut, const float4* __restrict__ emb4){
    int i = blockIdx.x*blockDim.x + threadIdx.x;
    if (i < NN*32){
        int n = i >> 5, q = i & 31;
        float4 v = emb4[ut[n]*32 + q];
        ((float4*)g_x)[i] = v;
        split_store4(g_Ah, g_Al, (size_t)n*KK + 896 + q*4, v);
    }
}

// ---------------- per-layer aggregate: warp per segment --------------------
__global__ void k_agg(){
    int w = (blockIdx.x*blockDim.x + threadIdx.x) >> 5;
    int lane = threadIdx.x & 31;
    if (w >= NS) return;
    int beg = g_start[w], end = g_start[w+1];
    const float4* x4 = (const float4*)g_x;
    float4 acc = make_float4(0.f, 0.f, 0.f, 0.f);
    int j = beg;
    for (; j + 1 < end; j += 2){
        int2 e0 = g_edge[j];
        int2 e1 = g_edge[j+1];
        float w0 = __int_as_float(e0.y);
        float w1 = __int_as_float(e1.y);
        float4 v0 = __ldg(&x4[(size_t)e0.x*32 + lane]);
        float4 v1 = __ldg(&x4[(size_t)e1.x*32 + lane]);
        acc.x += w0*v0.x + w1*v1.x;
        acc.y += w0*v0.y + w1*v1.y;
        acc.z += w0*v0.z + w1*v1.z;
        acc.w += w0*v0.w + w1*v1.w;
    }
    if (j < end){
        int2 e0 = g_edge[j];
        float w0 = __int_as_float(e0.y);
        float4 v0 = __ldg(&x4[(size_t)e0.x*32 + lane]);
        acc.x += w0*v0.x; acc.y += w0*v0.y; acc.z += w0*v0.z; acc.w += w0*v0.w;
    }
    int n = w / RR, r = w - n*RR;
    split_store4(g_Ah, g_Al, (size_t)n*KK + r*DD + lane*4, acc);
}

// ---------------- weight transpose + split, ALL layers ---------------------
__global__ void k_prepW(const float* __restrict__ Wrel, const float* __restrict__ brel,
                        const float* __restrict__ Wloop, const float* __restrict__ bloop){
    int i = blockIdx.x*blockDim.x + threadIdx.x;
    if (i < NLAYERS*KK*DD){
        int layer = i / (KK*DD);
        int rem   = i - layer*(KK*DD);
        int n = rem >> 10, k = rem & 1023;
        float v = (k < 896)
            ? Wrel [(size_t)layer*896*128 + (size_t)k*128 + n]
            : Wloop[(size_t)layer*128*128 + (size_t)(k-896)*128 + n];
        __nv_bfloat16 h = __float2bfloat16(v);
        g_Bh3[layer][rem] = h;
        g_Bl3[layer][rem] = __float2bfloat16(v - __bfloat162float(h));
    }
    if (i < NLAYERS*DD){
        int layer = i / DD, c = i - layer*DD;
        g_bias3[layer][c] = brel[layer*DD + c] + bloop[layer*DD + c];
    }
}

// ---------------- pipelined mma.sync GEMM ----------------------------------
// C[128tile,128] = A[.,1024] * Wt^T, split-3 bf16, fp32 accum.
// 2-stage cp.async pipeline; stage = 4 tiles of 128x64 bf16 (SW128), 64KB.
__global__ void __launch_bounds__(256, 1) k_gemm_mma(float* __restrict__ xout,
                                                     int writeAux, int layer){
    extern __shared__ char dsm[];
    uint32_t sbase = smem_u32(dsm);

    int tid  = threadIdx.x;
    int wid  = tid >> 5;
    int lane = tid & 31;
    int wm   = wid & 3;      // 4 warps along M
    int wn   = wid >> 2;     // 2 warps along N
    int m0   = blockIdx.x * 128;

    const char* srcs[4] = {
        (const char*)g_Ah + (size_t)m0*2048,
        (const char*)g_Al + (size_t)m0*2048,
        (const char*)g_Bh3[layer],
        (const char*)g_Bl3[layer] };

    // per-thread load slots: 4 per tile, 4 tiles
    int l_row[4], l_seg[4];
    #pragma unroll
    for (int i = 0; i < 4; i++){
        int idx = tid + i*256;
        l_row[i] = idx >> 3;
        l_seg[i] = (idx & 7) * 16;
    }

    // un-swizzled ldsm components (swizzle applied per K-step)
    uint32_t a_rowb = (uint32_t)(((lane & 7) + ((lane >> 3) & 1) * 8 + wm * 32) * 128);
    uint32_t a_kb   = ((lane >> 4) & 1) * 16;
    uint32_t b_rowb = (uint32_t)(((lane & 7) + ((lane >> 4) & 1) * 8 + wn * 64) * 128);
    uint32_t b_kb   = ((lane >> 3) & 1) * 16;

    float acc[2][8][4];
    #pragma unroll
    for (int mt = 0; mt < 2; mt++)
        #pragma unroll
        for (int nt = 0; nt < 8; nt++)
            #pragma unroll
            for (int q = 0; q < 4; q++) acc[mt][nt][q] = 0.f;

    // issue async loads of chunk kc into stage
    auto issue = [&](int kc, int stage){
        size_t kbyte = (size_t)kc * 128;
        uint32_t sb = sbase + stage*STAGE_BYTES;
        #pragma unroll
        for (int t4 = 0; t4 < 4; t4++){
            #pragma unroll
            for (int i = 0; i < 4; i++){
                const char* src = srcs[t4] + (size_t)l_row[i]*2048 + kbyte + l_seg[i];
                uint32_t dst = sb + t4*16384 + SMEM_SWIZZLE_128B(l_row[i]*128 + l_seg[i]);
                CP_ASYNC16(dst, src);
            }
        }
    };

    issue(0, 0);
    CP_COMMIT();

    for (int kc = 0; kc < NCHUNK; kc++){
        if (kc + 1 < NCHUNK){
            issue(kc + 1, (kc + 1) & 1);
            CP_COMMIT();
            CP_WAIT1();
        } else {
            CP_WAIT0();
        }
        __syncthreads();

        uint32_t sb  = sbase + (kc & 1)*STAGE_BYTES;
        uint32_t sAH = sb, sAL = sb + 16384, sBH = sb + 32768, sBL = sb + 49152;

        #pragma unroll
        for (int ks = 0; ks < 4; ks++){
            uint32_t koff = ks * 32;
            uint32_t a_off = SMEM_SWIZZLE_128B(a_rowb + a_kb + koff);
            uint32_t b_off = SMEM_SWIZZLE_128B(b_rowb + b_kb + koff);
            uint32_t ah[2][4], al[2][4];
            #pragma unroll
            for (int mt = 0; mt < 2; mt++){
                ldsm4(ah[mt], sAH + a_off + mt*2048);
                ldsm4(al[mt], sAL + a_off + mt*2048);
            }
            #pragma unroll
            for (int np = 0; np < 4; np++){
                uint32_t bh[4], bl[4];
                ldsm4(bh, sBH + b_off + np*2048);
                ldsm4(bl, sBL + b_off + np*2048);
                #pragma unroll
                for (int half = 0; half < 2; half++){
                    int nt = np*2 + half;
                    #pragma unroll
                    for (int mt = 0; mt < 2; mt++){
                        mma16816(acc[mt][nt], ah[mt], bh + half*2);
                        mma16816(acc[mt][nt], al[mt], bh + half*2);
                        mma16816(acc[mt][nt], ah[mt], bl + half*2);
                    }
                }
            }
        }
        __syncthreads();
    }

    // epilogue: bias + relu
    const float* bias = g_bias3[layer];
    int qrow = lane >> 2;            // 0..7
    int qcol = (lane & 3) * 2;       // 0,2,4,6
    #pragma unroll
    for (int mt = 0; mt < 2; mt++){
        #pragma unroll
        for (int nt = 0; nt < 8; nt++){
            int col  = wn*64 + nt*8 + qcol;
            float2 bb = *(const float2*)&bias[col];
            int r0 = m0 + wm*32 + mt*16 + qrow;
            int r1 = r0 + 8;
            float v00 = fmaxf(acc[mt][nt][0] + bb.x, 0.f);
            float v01 = fmaxf(acc[mt][nt][1] + bb.y, 0.f);
            float v10 = fmaxf(acc[mt][nt][2] + bb.x, 0.f);
            float v11 = fmaxf(acc[mt][nt][3] + bb.y, 0.f);
            if (writeAux){
                if (r0 < NN){
                    *(float2*)&g_x[(size_t)r0*DD + col] = make_float2(v00, v01);
                    split_store2((size_t)r0*KK + 896 + col, v00, v01);
                }
                if (r1 < NN){
                    *(float2*)&g_x[(size_t)r1*DD + col] = make_float2(v10, v11);
                    split_store2((size_t)r1*KK + 896 + col, v10, v11);
                }
            } else {
                if (r0 < NN) *(float2*)&xout[(size_t)r0*DD + col] = make_float2(v00, v01);
                if (r1 < NN) *(float2*)&xout[(size_t)r1*DD + col] = make_float2(v10, v11);
            }
        }
    }
}

// ---------------- graph pooling --------------------------------------------
__global__ void k_zero_out(float* __restrict__ out){
    int i = blockIdx.x*blockDim.x + threadIdx.x;
    if (i < GG*DD) out[i] = 0.f;
}
__device__ __forceinline__ int lowerb(const int* __restrict__ a, int n, int key){
    int lo = 0, hi = n;
    while (lo < hi){
        int mid = (lo + hi) >> 1;
        if (a[mid] < key) lo = mid + 1; else hi = mid;
    }
    return lo;
}
__global__ void k_gsum(const int* __restrict__ n2g, const float* __restrict__ x,
                       float* __restrict__ out){
    int g = blockIdx.x / GSPLIT, c = blockIdx.x % GSPLIT, t = threadIdx.x;
    int lo = lowerb(n2g, NN, g);
    int hi = lowerb(n2g, NN, g+1);
    int len = hi - lo;
    int per = (len + GSPLIT - 1) / GSPLIT;
    int s = lo + c*per;
    int e = min(s + per, hi);
    float acc = 0.f;
    for (int n = s; n < e; n++) acc += x[(size_t)n*DD + t];
    if (e > s) atomicAdd(&out[g*DD + t], acc);
}

// ---------------- launcher --------------------------------------------------
extern "C" void kernel_launch(void* const* d_in, const int* in_sizes, int n_in,
                              void* d_out, int out_size){
    const int*   unit_type   = (const int*)  d_in[0];
    const int*   node_in     = (const int*)  d_in[1];
    const int*   node_out    = (const int*)  d_in[2];
    const int*   relation    = (const int*)  d_in[3];
    const float* edge_weight = (const float*)d_in[4];
    const int*   node2graph  = (const int*)  d_in[5];
    const float* emb         = (const float*)d_in[6];
    const float* W_rel       = (const float*)d_in[7];
    const float* b_rel       = (const float*)d_in[8];
    const float* W_loop      = (const float*)d_in[9];
    const float* b_loop      = (const float*)d_in[10];

    float* out   = (float*)d_out;
    float* x_out = out + GG*DD;

    // idempotent, capture-safe; no static guard (harness rule)
    cudaFuncSetAttribute(k_gemm_mma, cudaFuncAttributeMaxDynamicSharedMemorySize, GEMM_SMEM);

    int nb_ns = (NS + 1023) / 1024;  // 342

    k_zero_cnt<<<nb_ns, 1024>>>();
    k_hist<<<(EE + 255)/256, 256>>>(node_out, relation);
    k_scan1<<<nb_ns, 1024>>>();
    k_scan2<<<1, 512>>>(nb_ns);
    k_scan3<<<nb_ns, 1024>>>();
    k_scatter<<<(EE + 255)/256, 256>>>(node_in, node_out, relation, edge_weight);

    k_embed<<<(NN*32 + 255)/256, 256>>>(unit_type, (const float4*)emb);
    k_prepW<<<(NLAYERS*KK*DD + 255)/256, 256>>>(W_rel, b_rel, W_loop, b_loop);

    for (int l = 0; l < NLAYERS; l++){
        k_agg<<<(NS*32 + 255)/256, 256>>>();
        if (l < NLAYERS - 1)
            k_gemm_mma<<<MTILES, 256, GEMM_SMEM>>>(nullptr, 1, l);
        else
            k_gemm_mma<<<MTILES, 256, GEMM_SMEM>>>(x_out, 0, l);
    }

    k_zero_out<<<(GG*DD + 255)/256, 256>>>(out);
    k_gsum<<<GG*GSPLIT, 128>>>(node2graph, x_out, out);
}

// round 7
// speedup vs baseline: 2.2385x; 1.2671x over previous
#include <cuda_runtime.h>
#include <cuda_fp16.h>
#include <cstdint>

#define NN 50000
#define NPAD 50048          // 391 * 128
#define EE 1600000
#define RR 7
#define DD 128
#define GG 64
#define NS (NN*RR)
#define KK 1024             // R*D + D
#define NLAYERS 3
#define GSPLIT 16
#define NCHUNK 16           // K chunks of 64
#define MTILES (NPAD/128)   // 391
#define STAGE_BYTES 49152   // 3 tiles x 16KB
#define GEMM_SMEM (2*STAGE_BYTES)

// ---------------- scratch (device globals; zero-initialized at load) -------
__device__ __align__(16) __half g_Af[(size_t)NPAD*KK];        // A in fp16 (102MB)
__device__ __align__(16) float  g_x[(size_t)NN*DD];
__device__ __align__(16) __half g_Bh3[NLAYERS][DD*KK];        // Wt hi [n][k]
__device__ __align__(16) __half g_Bl3[NLAYERS][DD*KK];        // Wt lo
__device__ __align__(16) float  g_bias3[NLAYERS][DD];
__device__ int   g_cnt[NS];
__device__ int   g_start[NS+1];
__device__ int   g_cur[NS];
__device__ __align__(8) int2 g_edge[EE];   // (src, ew bits)
__device__ int   g_bsum[512];

// ---------------- helpers ---------------------------------------------------
__device__ __forceinline__ uint32_t smem_u32(const void* p){
    uint32_t a;
    asm("{ .reg .u64 t; cvta.to.shared.u64 t, %1; cvt.u32.u64 %0, t; }" : "=r"(a) : "l"(p));
    return a;
}
#define SMEM_SWIZZLE_128B(o) ((o) ^ (((o) >> 3) & 0x70))

#define CP_ASYNC16(dst, src) \
    asm volatile("cp.async.cg.shared.global [%0], [%1], 16;" :: "r"(dst), "l"(src))
#define CP_COMMIT() asm volatile("cp.async.commit_group;" ::: "memory")
#define CP_WAIT1()  asm volatile("cp.async.wait_group 1;" ::: "memory")
#define CP_WAIT0()  asm volatile("cp.async.wait_group 0;" ::: "memory")

__device__ __forceinline__ void ldsm4(uint32_t* r, uint32_t addr){
    asm volatile("ldmatrix.sync.aligned.m8n8.x4.shared.b16 {%0,%1,%2,%3}, [%4];"
        : "=r"(r[0]), "=r"(r[1]), "=r"(r[2]), "=r"(r[3]) : "r"(addr));
}
__device__ __forceinline__ void mma16816(float* c, const uint32_t* a, const uint32_t* b){
    asm volatile("mma.sync.aligned.m16n8k16.row.col.f32.f16.f16.f32 "
        "{%0,%1,%2,%3}, {%4,%5,%6,%7}, {%8,%9}, {%0,%1,%2,%3};"
        : "+f"(c[0]), "+f"(c[1]), "+f"(c[2]), "+f"(c[3])
        : "r"(a[0]), "r"(a[1]), "r"(a[2]), "r"(a[3]), "r"(b[0]), "r"(b[1]));
}

__device__ __forceinline__ void h_store4(size_t off, float4 v){
    *(__half2*)(g_Af + off)     = __floats2half2_rn(v.x, v.y);
    *(__half2*)(g_Af + off + 2) = __floats2half2_rn(v.z, v.w);
}

// ---------------- CSR build (launch order tuned so launch #5 = k_agg) ------
// launch 0: embed + zero g_cnt
__global__ void k_embed_zero(const int* __restrict__ ut, const float4* __restrict__ emb4){
    int i = blockIdx.x*blockDim.x + threadIdx.x;
    if (i < NS) g_cnt[i] = 0;
    if (i < NN*32){
        int n = i >> 5, q = i & 31;
        float4 v = emb4[ut[n]*32 + q];
        ((float4*)g_x)[i] = v;
        h_store4((size_t)n*KK + 896 + q*4, v);
    }
}
// launch 1
__global__ void k_hist(const int* __restrict__ nout, const int* __restrict__ rel){
    int e = blockIdx.x*blockDim.x + threadIdx.x;
    if (e < EE) atomicAdd(&g_cnt[nout[e]*RR + rel[e]], 1);
}
// launch 2
__global__ void k_scan1(){
    __shared__ int sm[1024];
    int t = threadIdx.x;
    int i = blockIdx.x*1024 + t;
    int v = (i < NS) ? g_cnt[i] : 0;
    sm[t] = v; __syncthreads();
    for (int off = 1; off < 1024; off <<= 1){
        int u = (t >= off) ? sm[t-off] : 0;
        __syncthreads();
        sm[t] += u;
        __syncthreads();
    }
    if (i < NS) g_start[i] = sm[t] - v;
    if (t == 1023) g_bsum[blockIdx.x] = sm[t];
}
// launch 3: fused scan2+scan3 (each block redundantly scans the block sums)
__global__ void k_scan23(int nb){
    __shared__ int sm[512];
    int t = threadIdx.x;
    if (t < 512) sm[t] = (t < nb) ? g_bsum[t] : 0;
    __syncthreads();
    for (int off = 1; off < 512; off <<= 1){
        int u = 0;
        if (t < 512 && t >= off) u = sm[t-off];
        __syncthreads();
        if (t < 512) sm[t] += u;
        __syncthreads();
    }
    int boff = sm[blockIdx.x] - g_bsum[blockIdx.x];   // exclusive prefix of this block
    int i = blockIdx.x*1024 + t;
    if (i < NS){
        int s = g_start[i] + boff;
        g_start[i] = s;
        g_cur[i]   = s;
    }
    if (i == 0) g_start[NS] = EE;
}
// launch 4
__global__ void k_scatter(const int* __restrict__ nin, const int* __restrict__ nout,
                          const int* __restrict__ rel, const float* __restrict__ ewt){
    int e = blockIdx.x*blockDim.x + threadIdx.x;
    if (e < EE){
        int s = nout[e]*RR + rel[e];
        int p = atomicAdd(&g_cur[s], 1);
        g_edge[p] = make_int2(nin[e], __float_as_int(ewt[e]));
    }
}

// ---------------- per-layer aggregate (launch 5 = profiled) ----------------
__global__ void k_agg(){
    int w = (blockIdx.x*blockDim.x + threadIdx.x) >> 5;
    int lane = threadIdx.x & 31;
    if (w >= NS) return;
    int beg = g_start[w], end = g_start[w+1];
    const float4* x4 = (const float4*)g_x;
    float4 acc = make_float4(0.f, 0.f, 0.f, 0.f);
    int j = beg;
    for (; j + 1 < end; j += 2){
        int2 e0 = g_edge[j];
        int2 e1 = g_edge[j+1];
        float w0 = __int_as_float(e0.y);
        float w1 = __int_as_float(e1.y);
        float4 v0 = __ldg(&x4[(size_t)e0.x*32 + lane]);
        float4 v1 = __ldg(&x4[(size_t)e1.x*32 + lane]);
        acc.x += w0*v0.x + w1*v1.x;
        acc.y += w0*v0.y + w1*v1.y;
        acc.z += w0*v0.z + w1*v1.z;
        acc.w += w0*v0.w + w1*v1.w;
    }
    if (j < end){
        int2 e0 = g_edge[j];
        float w0 = __int_as_float(e0.y);
        float4 v0 = __ldg(&x4[(size_t)e0.x*32 + lane]);
        acc.x += w0*v0.x; acc.y += w0*v0.y; acc.z += w0*v0.z; acc.w += w0*v0.w;
    }
    int n = w / RR, r = w - n*RR;
    h_store4((size_t)n*KK + r*DD + lane*4, acc);
}

// ---------------- weight transpose + fp16 split-2, ALL layers --------------
__global__ void k_prepW(const float* __restrict__ Wrel, const float* __restrict__ brel,
                        const float* __restrict__ Wloop, const float* __restrict__ bloop){
    int i = blockIdx.x*blockDim.x + threadIdx.x;
    if (i < NLAYERS*KK*DD){
        int layer = i / (KK*DD);
        int rem   = i - layer*(KK*DD);
        int n = rem >> 10, k = rem & 1023;
        float v = (k < 896)
            ? Wrel [(size_t)layer*896*128 + (size_t)k*128 + n]
            : Wloop[(size_t)layer*128*128 + (size_t)(k-896)*128 + n];
        __half h = __float2half_rn(v);
        g_Bh3[layer][rem] = h;
        g_Bl3[layer][rem] = __float2half_rn(v - __half2float(h));
    }
    if (i < NLAYERS*DD){
        int layer = i / DD, c = i - layer*DD;
        g_bias3[layer][c] = brel[layer*DD + c] + bloop[layer*DD + c];
    }
}

// ---------------- pipelined mma.sync GEMM (fp16 split-2) -------------------
// C[128tile,128] = Af * (Bh + Bl)^T, fp32 accum.
// 2-stage cp.async; stage = 3 tiles of 128x64 fp16 (SW128), 48KB. 2 CTAs/SM.
__global__ void __launch_bounds__(256, 2) k_gemm_mma(float* __restrict__ xout,
                                                     int writeAux, int layer){
    extern __shared__ char dsm[];
    uint32_t sbase = smem_u32(dsm);

    int tid  = threadIdx.x;
    int wid  = tid >> 5;
    int lane = tid & 31;
    int wm   = wid & 3;      // 4 warps along M
    int wn   = wid >> 2;     // 2 warps along N
    int m0   = blockIdx.x * 128;

    const char* srcs[3] = {
        (const char*)g_Af + (size_t)m0*2048,
        (const char*)g_Bh3[layer],
        (const char*)g_Bl3[layer] };

    int l_row[4], l_seg[4];
    #pragma unroll
    for (int i = 0; i < 4; i++){
        int idx = tid + i*256;
        l_row[i] = idx >> 3;
        l_seg[i] = (idx & 7) * 16;
    }

    uint32_t a_rowb = (uint32_t)(((lane & 7) + ((lane >> 3) & 1) * 8 + wm * 32) * 128);
    uint32_t a_kb   = ((lane >> 4) & 1) * 16;
    uint32_t b_rowb = (uint32_t)(((lane & 7) + ((lane >> 4) & 1) * 8 + wn * 64) * 128);
    uint32_t b_kb   = ((lane >> 3) & 1) * 16;

    float acc[2][8][4];
    #pragma unroll
    for (int mt = 0; mt < 2; mt++)
        #pragma unroll
        for (int nt = 0; nt < 8; nt++)
            #pragma unroll
            for (int q = 0; q < 4; q++) acc[mt][nt][q] = 0.f;

    auto issue = [&](int kc, int stage){
        size_t kbyte = (size_t)kc * 128;
        uint32_t sb = sbase + stage*STAGE_BYTES;
        #pragma unroll
        for (int t3 = 0; t3 < 3; t3++){
            #pragma unroll
            for (int i = 0; i < 4; i++){
                const char* src = srcs[t3] + (size_t)l_row[i]*2048 + kbyte + l_seg[i];
                uint32_t dst = sb + t3*16384 + SMEM_SWIZZLE_128B(l_row[i]*128 + l_seg[i]);
                CP_ASYNC16(dst, src);
            }
        }
    };

    issue(0, 0);
    CP_COMMIT();

    for (int kc = 0; kc < NCHUNK; kc++){
        if (kc + 1 < NCHUNK){
            issue(kc + 1, (kc + 1) & 1);
            CP_COMMIT();
            CP_WAIT1();
        } else {
            CP_WAIT0();
        }
        __syncthreads();

        uint32_t sb  = sbase + (kc & 1)*STAGE_BYTES;
        uint32_t sAF = sb, sBH = sb + 16384, sBL = sb + 32768;

        #pragma unroll
        for (int ks = 0; ks < 4; ks++){
            uint32_t koff = ks * 32;
            uint32_t a_off = SMEM_SWIZZLE_128B(a_rowb + a_kb + koff);
            uint32_t b_off = SMEM_SWIZZLE_128B(b_rowb + b_kb + koff);
            uint32_t af[2][4];
            #pragma unroll
            for (int mt = 0; mt < 2; mt++)
                ldsm4(af[mt], sAF + a_off + mt*2048);
            #pragma unroll
            for (int np = 0; np < 4; np++){
                uint32_t bh[4], bl[4];
                ldsm4(bh, sBH + b_off + np*2048);
                ldsm4(bl, sBL + b_off + np*2048);
                #pragma unroll
                for (int half = 0; half < 2; half++){
                    int nt = np*2 + half;
                    #pragma unroll
                    for (int mt = 0; mt < 2; mt++){
                        mma16816(acc[mt][nt], af[mt], bh + half*2);
                        mma16816(acc[mt][nt], af[mt], bl + half*2);
                    }
                }
            }
        }
        __syncthreads();
    }

    // epilogue: bias + relu
    const float* bias = g_bias3[layer];
    int qrow = lane >> 2;            // 0..7
    int qcol = (lane & 3) * 2;       // 0,2,4,6
    #pragma unroll
    for (int mt = 0; mt < 2; mt++){
        #pragma unroll
        for (int nt = 0; nt < 8; nt++){
            int col  = wn*64 + nt*8 + qcol;
            float2 bb = *(const float2*)&bias[col];
            int r0 = m0 + wm*32 + mt*16 + qrow;
            int r1 = r0 + 8;
            float v00 = fmaxf(acc[mt][nt][0] + bb.x, 0.f);
            float v01 = fmaxf(acc[mt][nt][1] + bb.y, 0.f);
            float v10 = fmaxf(acc[mt][nt][2] + bb.x, 0.f);
            float v11 = fmaxf(acc[mt][nt][3] + bb.y, 0.f);
            if (writeAux){
                if (r0 < NN){
                    *(float2*)&g_x[(size_t)r0*DD + col] = make_float2(v00, v01);
                    *(__half2*)&g_Af[(size_t)r0*KK + 896 + col] = __floats2half2_rn(v00, v01);
                }
                if (r1 < NN){
                    *(float2*)&g_x[(size_t)r1*DD + col] = make_float2(v10, v11);
                    *(__half2*)&g_Af[(size_t)r1*KK + 896 + col] = __floats2half2_rn(v10, v11);
                }
            } else {
                if (r0 < NN) *(float2*)&xout[(size_t)r0*DD + col] = make_float2(v00, v01);
                if (r1 < NN) *(float2*)&xout[(size_t)r1*DD + col] = make_float2(v10, v11);
            }
        }
    }
}

// ---------------- graph pooling --------------------------------------------
__global__ void k_zero_out(float* __restrict__ out){
    int i = blockIdx.x*blockDim.x + threadIdx.x;
    if (i < GG*DD) out[i] = 0.f;
}
__device__ __forceinline__ int lowerb(const int* __restrict__ a, int n, int key){
    int lo = 0, hi = n;
    while (lo < hi){
        int mid = (lo + hi) >> 1;
        if (a[mid] < key) lo = mid + 1; else hi = mid;
    }
    return lo;
}
__global__ void k_gsum(const int* __restrict__ n2g, const float* __restrict__ x,
                       float* __restrict__ out){
    int g = blockIdx.x / GSPLIT, c = blockIdx.x % GSPLIT, t = threadIdx.x;
    int lo = lowerb(n2g, NN, g);
    int hi = lowerb(n2g, NN, g+1);
    int len = hi - lo;
    int per = (len + GSPLIT - 1) / GSPLIT;
    int s = lo + c*per;
    int e = min(s + per, hi);
    float acc = 0.f;
    for (int n = s; n < e; n++) acc += x[(size_t)n*DD + t];
    if (e > s) atomicAdd(&out[g*DD + t], acc);
}

// ---------------- launcher --------------------------------------------------
extern "C" void kernel_launch(void* const* d_in, const int* in_sizes, int n_in,
                              void* d_out, int out_size){
    const int*   unit_type   = (const int*)  d_in[0];
    const int*   node_in     = (const int*)  d_in[1];
    const int*   node_out    = (const int*)  d_in[2];
    const int*   relation    = (const int*)  d_in[3];
    const float* edge_weight = (const float*)d_in[4];
    const int*   node2graph  = (const int*)  d_in[5];
    const float* emb         = (const float*)d_in[6];
    const float* W_rel       = (const float*)d_in[7];
    const float* b_rel       = (const float*)d_in[8];
    const float* W_loop      = (const float*)d_in[9];
    const float* b_loop      = (const float*)d_in[10];

    float* out   = (float*)d_out;
    float* x_out = out + GG*DD;

    // idempotent, capture-safe; no static guard (harness rule)
    cudaFuncSetAttribute(k_gemm_mma, cudaFuncAttributeMaxDynamicSharedMemorySize, GEMM_SMEM);

    int nb_ns = (NS + 1023) / 1024;  // 342

    // launches 0..4: embed+zero, hist, scan1, scan23, scatter
    k_embed_zero<<<(NN*32 + 255)/256, 256>>>(unit_type, (const float4*)emb);
    k_hist<<<(EE + 255)/256, 256>>>(node_out, relation);
    k_scan1<<<nb_ns, 1024>>>();
    k_scan23<<<nb_ns, 1024>>>(nb_ns);
    k_scatter<<<(EE + 255)/256, 256>>>(node_in, node_out, relation, edge_weight);

    for (int l = 0; l < NLAYERS; l++){
        k_agg<<<(NS*32 + 255)/256, 256>>>();          // launch 5 on l==0 (profiled)
        if (l == 0)
            k_prepW<<<(NLAYERS*KK*DD + 255)/256, 256>>>(W_rel, b_rel, W_loop, b_loop);
        if (l < NLAYERS - 1)
            k_gemm_mma<<<MTILES, 256, GEMM_SMEM>>>(nullptr, 1, l);
        else
            k_gemm_mma<<<MTILES, 256, GEMM_SMEM>>>(x_out, 0, l);
    }

    k_zero_out<<<(GG*DD + 255)/256, 256>>>(out);
    k_gsum<<<GG*GSPLIT, 128>>>(node2graph, x_out, out);
}

// round 8
// speedup vs baseline: 2.3189x; 1.0359x over previous
#include <cuda_runtime.h>
#include <cuda_fp16.h>
#include <cstdint>

#define NN 50000
#define NPAD 50048          // 391 * 128
#define EE 1600000
#define RR 7
#define DD 128
#define GG 64
#define NS (NN*RR)
#define KK 1024             // R*D + D
#define NLAYERS 3
#define GSPLIT 16
#define NCHUNK 16           // K chunks of 64
#define MTILES (NPAD/128)   // 391
#define STAGE_BYTES 49152   // 3 tiles x 16KB
#define GEMM_SMEM (2*STAGE_BYTES)

// ---------------- scratch (device globals; zero-initialized at load) -------
__device__ __align__(16) __half g_Af[(size_t)NPAD*KK];        // A in fp16 (102MB)
__device__ __align__(16) __half g_xh[(size_t)NN*DD];          // x in fp16 (12.8MB)
__device__ __align__(16) __half g_Bh3[NLAYERS][DD*KK];        // Wt hi [n][k]
__device__ __align__(16) __half g_Bl3[NLAYERS][DD*KK];        // Wt lo
__device__ __align__(16) float  g_bias3[NLAYERS][DD];
__device__ int   g_cnt[NS];
__device__ int   g_start[NS+1];
__device__ int   g_cur[NS];
__device__ __align__(8) int2 g_edge[EE];   // (src, ew bits)
__device__ int   g_bsum[512];

// ---------------- helpers ---------------------------------------------------
__device__ __forceinline__ uint32_t smem_u32(const void* p){
    uint32_t a;
    asm("{ .reg .u64 t; cvta.to.shared.u64 t, %1; cvt.u32.u64 %0, t; }" : "=r"(a) : "l"(p));
    return a;
}
#define SMEM_SWIZZLE_128B(o) ((o) ^ (((o) >> 3) & 0x70))

#define CP_ASYNC16(dst, src) \
    asm volatile("cp.async.cg.shared.global [%0], [%1], 16;" :: "r"(dst), "l"(src))
#define CP_COMMIT() asm volatile("cp.async.commit_group;" ::: "memory")
#define CP_WAIT1()  asm volatile("cp.async.wait_group 1;" ::: "memory")
#define CP_WAIT0()  asm volatile("cp.async.wait_group 0;" ::: "memory")

__device__ __forceinline__ void ldsm4(uint32_t* r, uint32_t addr){
    asm volatile("ldmatrix.sync.aligned.m8n8.x4.shared.b16 {%0,%1,%2,%3}, [%4];"
        : "=r"(r[0]), "=r"(r[1]), "=r"(r[2]), "=r"(r[3]) : "r"(addr));
}
__device__ __forceinline__ void mma16816(float* c, const uint32_t* a, const uint32_t* b){
    asm volatile("mma.sync.aligned.m16n8k16.row.col.f32.f16.f16.f32 "
        "{%0,%1,%2,%3}, {%4,%5,%6,%7}, {%8,%9}, {%0,%1,%2,%3};"
        : "+f"(c[0]), "+f"(c[1]), "+f"(c[2]), "+f"(c[3])
        : "r"(a[0]), "r"(a[1]), "r"(a[2]), "r"(a[3]), "r"(b[0]), "r"(b[1]));
}

__device__ __forceinline__ void h_store4(size_t off, float4 v){
    *(__half2*)(g_Af + off)     = __floats2half2_rn(v.x, v.y);
    *(__half2*)(g_Af + off + 2) = __floats2half2_rn(v.z, v.w);
}

// ---------------- launch 0: embed (fp16 x + A aux cols) + zero g_cnt -------
__global__ void k_embed_zero(const int* __restrict__ ut, const float4* __restrict__ emb4){
    int i = blockIdx.x*blockDim.x + threadIdx.x;
    if (i < NS) g_cnt[i] = 0;
    if (i < NN*32){
        int n = i >> 5, q = i & 31;
        float4 v = emb4[ut[n]*32 + q];
        __half2 h01 = __floats2half2_rn(v.x, v.y);
        __half2 h23 = __floats2half2_rn(v.z, v.w);
        *(__half2*)(g_xh + (size_t)n*DD + q*4)     = h01;
        *(__half2*)(g_xh + (size_t)n*DD + q*4 + 2) = h23;
        *(__half2*)(g_Af + (size_t)n*KK + 896 + q*4)     = h01;
        *(__half2*)(g_Af + (size_t)n*KK + 896 + q*4 + 2) = h23;
    }
}
// launch 1
__global__ void k_hist(const int* __restrict__ nout, const int* __restrict__ rel){
    int e = blockIdx.x*blockDim.x + threadIdx.x;
    if (e < EE) atomicAdd(&g_cnt[nout[e]*RR + rel[e]], 1);
}
// launch 2
__global__ void k_scan1(){
    __shared__ int sm[1024];
    int t = threadIdx.x;
    int i = blockIdx.x*1024 + t;
    int v = (i < NS) ? g_cnt[i] : 0;
    sm[t] = v; __syncthreads();
    for (int off = 1; off < 1024; off <<= 1){
        int u = (t >= off) ? sm[t-off] : 0;
        __syncthreads();
        sm[t] += u;
        __syncthreads();
    }
    if (i < NS) g_start[i] = sm[t] - v;
    if (t == 1023) g_bsum[blockIdx.x] = sm[t];
}
// launch 3: fused scan2+scan3 (each block redundantly scans the block sums)
__global__ void k_scan23(int nb){
    __shared__ int sm[512];
    int t = threadIdx.x;
    if (t < 512) sm[t] = (t < nb) ? g_bsum[t] : 0;
    __syncthreads();
    for (int off = 1; off < 512; off <<= 1){
        int u = 0;
        if (t < 512 && t >= off) u = sm[t-off];
        __syncthreads();
        if (t < 512) sm[t] += u;
        __syncthreads();
    }
    int boff = sm[blockIdx.x] - g_bsum[blockIdx.x];   // exclusive prefix of this block
    int i = blockIdx.x*1024 + t;
    if (i < NS){
        int s = g_start[i] + boff;
        g_start[i] = s;
        g_cur[i]   = s;
    }
    if (i == 0) g_start[NS] = EE;
}
// launch 4
__global__ void k_scatter(const int* __restrict__ nin, const int* __restrict__ nout,
                          const int* __restrict__ rel, const float* __restrict__ ewt){
    int e = blockIdx.x*blockDim.x + threadIdx.x;
    if (e < EE){
        int s = nout[e]*RR + rel[e];
        int p = atomicAdd(&g_cur[s], 1);
        g_edge[p] = make_int2(nin[e], __float_as_int(ewt[e]));
    }
}

// ---------------- per-layer aggregate: warp/segment, fp16 gather -----------
__global__ void k_agg(){
    int w = (blockIdx.x*blockDim.x + threadIdx.x) >> 5;
    int lane = threadIdx.x & 31;
    if (w >= NS) return;
    int beg = g_start[w], end = g_start[w+1];
    const uint2* xh = (const uint2*)g_xh;   // 8B = 4 halves per lane; 32 lanes = 128 cols
    float4 acc = make_float4(0.f, 0.f, 0.f, 0.f);
    int j = beg;
    for (; j + 1 < end; j += 2){
        int2 e0 = g_edge[j];
        int2 e1 = g_edge[j+1];
        float w0 = __int_as_float(e0.y);
        float w1 = __int_as_float(e1.y);
        uint2 r0 = __ldg(&xh[(size_t)e0.x*32 + lane]);
        uint2 r1 = __ldg(&xh[(size_t)e1.x*32 + lane]);
        float2 a0 = __half22float2(*(__half2*)&r0.x);
        float2 b0 = __half22float2(*(__half2*)&r0.y);
        float2 a1 = __half22float2(*(__half2*)&r1.x);
        float2 b1 = __half22float2(*(__half2*)&r1.y);
        acc.x += w0*a0.x + w1*a1.x;
        acc.y += w0*a0.y + w1*a1.y;
        acc.z += w0*b0.x + w1*b1.x;
        acc.w += w0*b0.y + w1*b1.y;
    }
    if (j < end){
        int2 e0 = g_edge[j];
        float w0 = __int_as_float(e0.y);
        uint2 r0 = __ldg(&xh[(size_t)e0.x*32 + lane]);
        float2 a0 = __half22float2(*(__half2*)&r0.x);
        float2 b0 = __half22float2(*(__half2*)&r0.y);
        acc.x += w0*a0.x; acc.y += w0*a0.y; acc.z += w0*b0.x; acc.w += w0*b0.y;
    }
    int n = w / RR, r = w - n*RR;
    h_store4((size_t)n*KK + r*DD + lane*4, acc);
}

// ---------------- weight transpose + fp16 split-2, ALL layers --------------
__global__ void k_prepW(const float* __restrict__ Wrel, const float* __restrict__ brel,
                        const float* __restrict__ Wloop, const float* __restrict__ bloop){
    int i = blockIdx.x*blockDim.x + threadIdx.x;
    if (i < NLAYERS*KK*DD){
        int layer = i / (KK*DD);
        int rem   = i - layer*(KK*DD);
        int n = rem >> 10, k = rem & 1023;
        float v = (k < 896)
            ? Wrel [(size_t)layer*896*128 + (size_t)k*128 + n]
            : Wloop[(size_t)layer*128*128 + (size_t)(k-896)*128 + n];
        __half h = __float2half_rn(v);
        g_Bh3[layer][rem] = h;
        g_Bl3[layer][rem] = __float2half_rn(v - __half2float(h));
    }
    if (i < NLAYERS*DD){
        int layer = i / DD, c = i - layer*DD;
        g_bias3[layer][c] = brel[layer*DD + c] + bloop[layer*DD + c];
    }
}

// ---------------- pipelined mma.sync GEMM (fp16 split-2) -------------------
__global__ void __launch_bounds__(256, 2) k_gemm_mma(float* __restrict__ xout,
                                                     int writeAux, int layer){
    extern __shared__ char dsm[];
    uint32_t sbase = smem_u32(dsm);

    int tid  = threadIdx.x;
    int wid  = tid >> 5;
    int lane = tid & 31;
    int wm   = wid & 3;      // 4 warps along M
    int wn   = wid >> 2;     // 2 warps along N
    int m0   = blockIdx.x * 128;

    const char* srcs[3] = {
        (const char*)g_Af + (size_t)m0*2048,
        (const char*)g_Bh3[layer],
        (const char*)g_Bl3[layer] };

    int l_row[4], l_seg[4];
    #pragma unroll
    for (int i = 0; i < 4; i++){
        int idx = tid + i*256;
        l_row[i] = idx >> 3;
        l_seg[i] = (idx & 7) * 16;
    }

    uint32_t a_rowb = (uint32_t)(((lane & 7) + ((lane >> 3) & 1) * 8 + wm * 32) * 128);
    uint32_t a_kb   = ((lane >> 4) & 1) * 16;
    uint32_t b_rowb = (uint32_t)(((lane & 7) + ((lane >> 4) & 1) * 8 + wn * 64) * 128);
    uint32_t b_kb   = ((lane >> 3) & 1) * 16;

    float acc[2][8][4];
    #pragma unroll
    for (int mt = 0; mt < 2; mt++)
        #pragma unroll
        for (int nt = 0; nt < 8; nt++)
            #pragma unroll
            for (int q = 0; q < 4; q++) acc[mt][nt][q] = 0.f;

    auto issue = [&](int kc, int stage){
        size_t kbyte = (size_t)kc * 128;
        uint32_t sb = sbase + stage*STAGE_BYTES;
        #pragma unroll
        for (int t3 = 0; t3 < 3; t3++){
            #pragma unroll
            for (int i = 0; i < 4; i++){
                const char* src = srcs[t3] + (size_t)l_row[i]*2048 + kbyte + l_seg[i];
                uint32_t dst = sb + t3*16384 + SMEM_SWIZZLE_128B(l_row[i]*128 + l_seg[i]);
                CP_ASYNC16(dst, src);
            }
        }
    };

    issue(0, 0);
    CP_COMMIT();

    for (int kc = 0; kc < NCHUNK; kc++){
        if (kc + 1 < NCHUNK){
            issue(kc + 1, (kc + 1) & 1);
            CP_COMMIT();
            CP_WAIT1();
        } else {
            CP_WAIT0();
        }
        __syncthreads();

        uint32_t sb  = sbase + (kc & 1)*STAGE_BYTES;
        uint32_t sAF = sb, sBH = sb + 16384, sBL = sb + 32768;

        #pragma unroll
        for (int ks = 0; ks < 4; ks++){
            uint32_t koff = ks * 32;
            uint32_t a_off = SMEM_SWIZZLE_128B(a_rowb + a_kb + koff);
            uint32_t b_off = SMEM_SWIZZLE_128B(b_rowb + b_kb + koff);
            uint32_t af[2][4];
            #pragma unroll
            for (int mt = 0; mt < 2; mt++)
                ldsm4(af[mt], sAF + a_off + mt*2048);
            #pragma unroll
            for (int np = 0; np < 4; np++){
                uint32_t bh[4], bl[4];
                ldsm4(bh, sBH + b_off + np*2048);
                ldsm4(bl, sBL + b_off + np*2048);
                #pragma unroll
                for (int half = 0; half < 2; half++){
                    int nt = np*2 + half;
                    #pragma unroll
                    for (int mt = 0; mt < 2; mt++){
                        mma16816(acc[mt][nt], af[mt], bh + half*2);
                        mma16816(acc[mt][nt], af[mt], bl + half*2);
                    }
                }
            }
        }
        __syncthreads();
    }

    // epilogue: bias + relu
    const float* bias = g_bias3[layer];
    int qrow = lane >> 2;            // 0..7
    int qcol = (lane & 3) * 2;       // 0,2,4,6
    #pragma unroll
    for (int mt = 0; mt < 2; mt++){
        #pragma unroll
        for (int nt = 0; nt < 8; nt++){
            int col  = wn*64 + nt*8 + qcol;
            float2 bb = *(const float2*)&bias[col];
            int r0 = m0 + wm*32 + mt*16 + qrow;
            int r1 = r0 + 8;
            float v00 = fmaxf(acc[mt][nt][0] + bb.x, 0.f);
            float v01 = fmaxf(acc[mt][nt][1] + bb.y, 0.f);
            float v10 = fmaxf(acc[mt][nt][2] + bb.x, 0.f);
            float v11 = fmaxf(acc[mt][nt][3] + bb.y, 0.f);
            if (writeAux){
                if (r0 < NN){
                    __half2 h = __floats2half2_rn(v00, v01);
                    *(__half2*)&g_xh[(size_t)r0*DD + col] = h;
                    *(__half2*)&g_Af[(size_t)r0*KK + 896 + col] = h;
                }
                if (r1 < NN){
                    __half2 h = __floats2half2_rn(v10, v11);
                    *(__half2*)&g_xh[(size_t)r1*DD + col] = h;
                    *(__half2*)&g_Af[(size_t)r1*KK + 896 + col] = h;
                }
            } else {
                if (r0 < NN) *(float2*)&xout[(size_t)r0*DD + col] = make_float2(v00, v01);
                if (r1 < NN) *(float2*)&xout[(size_t)r1*DD + col] = make_float2(v10, v11);
            }
        }
    }
}

// ---------------- graph pooling --------------------------------------------
__global__ void k_zero_out(float* __restrict__ out){
    int i = blockIdx.x*blockDim.x + threadIdx.x;
    if (i < GG*DD) out[i] = 0.f;
}
__device__ __forceinline__ int lowerb(const int* __restrict__ a, int n, int key){
    int lo = 0, hi = n;
    while (lo < hi){
        int mid = (lo + hi) >> 1;
        if (a[mid] < key) lo = mid + 1; else hi = mid;
    }
    return lo;
}
__global__ void k_gsum(const int* __restrict__ n2g, const float* __restrict__ x,
                       float* __restrict__ out){
    int g = blockIdx.x / GSPLIT, c = blockIdx.x % GSPLIT, t = threadIdx.x;
    int lo = lowerb(n2g, NN, g);
    int hi = lowerb(n2g, NN, g+1);
    int len = hi - lo;
    int per = (len + GSPLIT - 1) / GSPLIT;
    int s = lo + c*per;
    int e = min(s + per, hi);
    float acc = 0.f;
    for (int n = s; n < e; n++) acc += x[(size_t)n*DD + t];
    if (e > s) atomicAdd(&out[g*DD + t], acc);
}

// ---------------- launcher --------------------------------------------------
extern "C" void kernel_launch(void* const* d_in, const int* in_sizes, int n_in,
                              void* d_out, int out_size){
    const int*   unit_type   = (const int*)  d_in[0];
    const int*   node_in     = (const int*)  d_in[1];
    const int*   node_out    = (const int*)  d_in[2];
    const int*   relation    = (const int*)  d_in[3];
    const float* edge_weight = (const float*)d_in[4];
    const int*   node2graph  = (const int*)  d_in[5];
    const float* emb         = (const float*)d_in[6];
    const float* W_rel       = (const float*)d_in[7];
    const float* b_rel       = (const float*)d_in[8];
    const float* W_loop      = (const float*)d_in[9];
    const float* b_loop      = (const float*)d_in[10];

    float* out   = (float*)d_out;
    float* x_out = out + GG*DD;

    // idempotent, capture-safe; no static guard (harness rule)
    cudaFuncSetAttribute(k_gemm_mma, cudaFuncAttributeMaxDynamicSharedMemorySize, GEMM_SMEM);

    int nb_ns = (NS + 1023) / 1024;  // 342

    k_embed_zero<<<(NN*32 + 255)/256, 256>>>(unit_type, (const float4*)emb);
    k_hist<<<(EE + 255)/256, 256>>>(node_out, relation);
    k_scan1<<<nb_ns, 1024>>>();
    k_scan23<<<nb_ns, 1024>>>(nb_ns);
    k_scatter<<<(EE + 255)/256, 256>>>(node_in, node_out, relation, edge_weight);

    for (int l = 0; l < NLAYERS; l++){
        k_agg<<<(NS*32 + 255)/256, 256>>>();
        if (l == 0)
            k_prepW<<<(NLAYERS*KK*DD + 255)/256, 256>>>(W_rel, b_rel, W_loop, b_loop);
        if (l < NLAYERS - 1)
            k_gemm_mma<<<MTILES, 256, GEMM_SMEM>>>(nullptr, 1, l);
        else
            k_gemm_mma<<<MTILES, 256, GEMM_SMEM>>>(x_out, 0, l);
    }

    k_zero_out<<<(GG*DD + 255)/256, 256>>>(out);
    k_gsum<<<GG*GSPLIT, 128>>>(node2graph, x_out, out);
}

// round 9
// speedup vs baseline: 3.0889x; 1.3321x over previous
#include <cuda_runtime.h>
#include <cuda_fp16.h>
#include <cstdint>

#define NN 50000
#define NPAD 50048          // 391 * 128
#define EE 1600000
#define RR 7
#define DD 128
#define GG 64
#define NS (NN*RR)
#define KK 1024             // R*D + D
#define NLAYERS 3
#define GSPLIT 16
#define NCHUNK 16           // K chunks of 64
#define MTILES (NPAD/128)   // 391
#define STAGE_BYTES 32768   // 2 tiles x 16KB
#define GEMM_SMEM (2*STAGE_BYTES)

// ---------------- scratch (device globals; zero-initialized at load) -------
__device__ __align__(16) __half g_Af[(size_t)NPAD*KK];        // A in fp16 (102MB)
__device__ __align__(16) __half g_xh[(size_t)NN*DD];          // x in fp16 (12.8MB)
__device__ __align__(16) __half g_Bf3[NLAYERS][DD*KK];        // Wt fp16 [n][k]
__device__ __align__(16) float  g_bias3[NLAYERS][DD];
__device__ int   g_cnt[NS];
__device__ int   g_start[NS+1];
__device__ int   g_cur[NS];
__device__ __align__(8) int2 g_edge[EE];   // (src, ew bits)
__device__ int   g_bsum[512];

// ---------------- helpers ---------------------------------------------------
__device__ __forceinline__ uint32_t smem_u32(const void* p){
    uint32_t a;
    asm("{ .reg .u64 t; cvta.to.shared.u64 t, %1; cvt.u32.u64 %0, t; }" : "=r"(a) : "l"(p));
    return a;
}
#define SMEM_SWIZZLE_128B(o) ((o) ^ (((o) >> 3) & 0x70))

#define CP_ASYNC16(dst, src) \
    asm volatile("cp.async.cg.shared.global [%0], [%1], 16;" :: "r"(dst), "l"(src))
#define CP_COMMIT() asm volatile("cp.async.commit_group;" ::: "memory")
#define CP_WAIT1()  asm volatile("cp.async.wait_group 1;" ::: "memory")
#define CP_WAIT0()  asm volatile("cp.async.wait_group 0;" ::: "memory")

__device__ __forceinline__ void ldsm4(uint32_t* r, uint32_t addr){
    asm volatile("ldmatrix.sync.aligned.m8n8.x4.shared.b16 {%0,%1,%2,%3}, [%4];"
        : "=r"(r[0]), "=r"(r[1]), "=r"(r[2]), "=r"(r[3]) : "r"(addr));
}
__device__ __forceinline__ void mma16816(float* c, const uint32_t* a, const uint32_t* b){
    asm volatile("mma.sync.aligned.m16n8k16.row.col.f32.f16.f16.f32 "
        "{%0,%1,%2,%3}, {%4,%5,%6,%7}, {%8,%9}, {%0,%1,%2,%3};"
        : "+f"(c[0]), "+f"(c[1]), "+f"(c[2]), "+f"(c[3])
        : "r"(a[0]), "r"(a[1]), "r"(a[2]), "r"(a[3]), "r"(b[0]), "r"(b[1]));
}

__device__ __forceinline__ void h_store4(size_t off, float4 v){
    *(__half2*)(g_Af + off)     = __floats2half2_rn(v.x, v.y);
    *(__half2*)(g_Af + off + 2) = __floats2half2_rn(v.z, v.w);
}

// ---------------- launch 0: embed (fp16 x + A aux cols) + zero g_cnt -------
__global__ void k_embed_zero(const int* __restrict__ ut, const float4* __restrict__ emb4){
    int i = blockIdx.x*blockDim.x + threadIdx.x;
    if (i < NS) g_cnt[i] = 0;
    if (i < NN*32){
        int n = i >> 5, q = i & 31;
        float4 v = emb4[ut[n]*32 + q];
        __half2 h01 = __floats2half2_rn(v.x, v.y);
        __half2 h23 = __floats2half2_rn(v.z, v.w);
        *(__half2*)(g_xh + (size_t)n*DD + q*4)     = h01;
        *(__half2*)(g_xh + (size_t)n*DD + q*4 + 2) = h23;
        *(__half2*)(g_Af + (size_t)n*KK + 896 + q*4)     = h01;
        *(__half2*)(g_Af + (size_t)n*KK + 896 + q*4 + 2) = h23;
    }
}
// launch 1
__global__ void k_hist(const int* __restrict__ nout, const int* __restrict__ rel){
    int e = blockIdx.x*blockDim.x + threadIdx.x;
    if (e < EE) atomicAdd(&g_cnt[nout[e]*RR + rel[e]], 1);
}
// launch 2
__global__ void k_scan1(){
    __shared__ int sm[1024];
    int t = threadIdx.x;
    int i = blockIdx.x*1024 + t;
    int v = (i < NS) ? g_cnt[i] : 0;
    sm[t] = v; __syncthreads();
    for (int off = 1; off < 1024; off <<= 1){
        int u = (t >= off) ? sm[t-off] : 0;
        __syncthreads();
        sm[t] += u;
        __syncthreads();
    }
    if (i < NS) g_start[i] = sm[t] - v;
    if (t == 1023) g_bsum[blockIdx.x] = sm[t];
}
// launch 3: fused scan2+scan3
__global__ void k_scan23(int nb){
    __shared__ int sm[512];
    int t = threadIdx.x;
    if (t < 512) sm[t] = (t < nb) ? g_bsum[t] : 0;
    __syncthreads();
    for (int off = 1; off < 512; off <<= 1){
        int u = 0;
        if (t < 512 && t >= off) u = sm[t-off];
        __syncthreads();
        if (t < 512) sm[t] += u;
        __syncthreads();
    }
    int boff = sm[blockIdx.x] - g_bsum[blockIdx.x];   // exclusive prefix of this block
    int i = blockIdx.x*1024 + t;
    if (i < NS){
        int s = g_start[i] + boff;
        g_start[i] = s;
        g_cur[i]   = s;
    }
    if (i == 0) g_start[NS] = EE;
}
// launch 4
__global__ void k_scatter(const int* __restrict__ nin, const int* __restrict__ nout,
                          const int* __restrict__ rel, const float* __restrict__ ewt){
    int e = blockIdx.x*blockDim.x + threadIdx.x;
    if (e < EE){
        int s = nout[e]*RR + rel[e];
        int p = atomicAdd(&g_cur[s], 1);
        g_edge[p] = make_int2(nin[e], __float_as_int(ewt[e]));
    }
}

// ---------------- per-layer aggregate: warp/segment, fp16 gather, unroll-4 -
__global__ void k_agg(){
    int w = (blockIdx.x*blockDim.x + threadIdx.x) >> 5;
    int lane = threadIdx.x & 31;
    if (w >= NS) return;
    int beg = __ldg(&g_start[w]), end = __ldg(&g_start[w+1]);
    const uint2* xh = (const uint2*)g_xh;   // 8B = 4 halves per lane; 32 lanes = 128 cols
    float4 acc = make_float4(0.f, 0.f, 0.f, 0.f);
    int j = beg;
    for (; j + 3 < end; j += 4){
        int2 e0 = __ldg(&g_edge[j]);
        int2 e1 = __ldg(&g_edge[j+1]);
        int2 e2 = __ldg(&g_edge[j+2]);
        int2 e3 = __ldg(&g_edge[j+3]);
        uint2 r0 = __ldg(&xh[(size_t)e0.x*32 + lane]);
        uint2 r1 = __ldg(&xh[(size_t)e1.x*32 + lane]);
        uint2 r2 = __ldg(&xh[(size_t)e2.x*32 + lane]);
        uint2 r3 = __ldg(&xh[(size_t)e3.x*32 + lane]);
        float w0 = __int_as_float(e0.y), w1 = __int_as_float(e1.y);
        float w2 = __int_as_float(e2.y), w3 = __int_as_float(e3.y);
        float2 a0 = __half22float2(*(__half2*)&r0.x), b0 = __half22float2(*(__half2*)&r0.y);
        float2 a1 = __half22float2(*(__half2*)&r1.x), b1 = __half22float2(*(__half2*)&r1.y);
        float2 a2 = __half22float2(*(__half2*)&r2.x), b2 = __half22float2(*(__half2*)&r2.y);
        float2 a3 = __half22float2(*(__half2*)&r3.x), b3 = __half22float2(*(__half2*)&r3.y);
        acc.x += w0*a0.x + w1*a1.x + w2*a2.x + w3*a3.x;
        acc.y += w0*a0.y + w1*a1.y + w2*a2.y + w3*a3.y;
        acc.z += w0*b0.x + w1*b1.x + w2*b2.x + w3*b3.x;
        acc.w += w0*b0.y + w1*b1.y + w2*b2.y + w3*b3.y;
    }
    for (; j < end; j++){
        int2 e0 = __ldg(&g_edge[j]);
        float w0 = __int_as_float(e0.y);
        uint2 r0 = __ldg(&xh[(size_t)e0.x*32 + lane]);
        float2 a0 = __half22float2(*(__half2*)&r0.x);
        float2 b0 = __half22float2(*(__half2*)&r0.y);
        acc.x += w0*a0.x; acc.y += w0*a0.y; acc.z += w0*b0.x; acc.w += w0*b0.y;
    }
    int n = w / RR, r = w - n*RR;
    h_store4((size_t)n*KK + r*DD + lane*4, acc);
}

// ---------------- weight transpose -> fp16, ALL layers ---------------------
__global__ void k_prepW(const float* __restrict__ Wrel, const float* __restrict__ brel,
                        const float* __restrict__ Wloop, const float* __restrict__ bloop){
    int i = blockIdx.x*blockDim.x + threadIdx.x;
    if (i < NLAYERS*KK*DD){
        int layer = i / (KK*DD);
        int rem   = i - layer*(KK*DD);
        int n = rem >> 10, k = rem & 1023;
        float v = (k < 896)
            ? Wrel [(size_t)layer*896*128 + (size_t)k*128 + n]
            : Wloop[(size_t)layer*128*128 + (size_t)(k-896)*128 + n];
        g_Bf3[layer][rem] = __float2half_rn(v);
    }
    if (i < NLAYERS*DD){
        int layer = i / DD, c = i - layer*DD;
        g_bias3[layer][c] = brel[layer*DD + c] + bloop[layer*DD + c];
    }
}

// ---------------- pipelined mma.sync GEMM (plain fp16) ---------------------
// C[128tile,128] = Af * Bf^T, fp32 accum. Stage = 2 tiles x 16KB. 2 CTAs/SM.
__global__ void __launch_bounds__(256, 2) k_gemm_mma(float* __restrict__ xout,
                                                     int writeAux, int layer){
    extern __shared__ char dsm[];
    uint32_t sbase = smem_u32(dsm);

    int tid  = threadIdx.x;
    int wid  = tid >> 5;
    int lane = tid & 31;
    int wm   = wid & 3;      // 4 warps along M
    int wn   = wid >> 2;     // 2 warps along N
    int m0   = blockIdx.x * 128;

    const char* srcs[2] = {
        (const char*)g_Af + (size_t)m0*2048,
        (const char*)g_Bf3[layer] };

    int l_row[4], l_seg[4];
    #pragma unroll
    for (int i = 0; i < 4; i++){
        int idx = tid + i*256;
        l_row[i] = idx >> 3;
        l_seg[i] = (idx & 7) * 16;
    }

    uint32_t a_rowb = (uint32_t)(((lane & 7) + ((lane >> 3) & 1) * 8 + wm * 32) * 128);
    uint32_t a_kb   = ((lane >> 4) & 1) * 16;
    uint32_t b_rowb = (uint32_t)(((lane & 7) + ((lane >> 4) & 1) * 8 + wn * 64) * 128);
    uint32_t b_kb   = ((lane >> 3) & 1) * 16;

    float acc[2][8][4];
    #pragma unroll
    for (int mt = 0; mt < 2; mt++)
        #pragma unroll
        for (int nt = 0; nt < 8; nt++)
            #pragma unroll
            for (int q = 0; q < 4; q++) acc[mt][nt][q] = 0.f;

    auto issue = [&](int kc, int stage){
        size_t kbyte = (size_t)kc * 128;
        uint32_t sb = sbase + stage*STAGE_BYTES;
        #pragma unroll
        for (int t2 = 0; t2 < 2; t2++){
            #pragma unroll
            for (int i = 0; i < 4; i++){
                const char* src = srcs[t2] + (size_t)l_row[i]*2048 + kbyte + l_seg[i];
                uint32_t dst = sb + t2*16384 + SMEM_SWIZZLE_128B(l_row[i]*128 + l_seg[i]);
                CP_ASYNC16(dst, src);
            }
        }
    };

    issue(0, 0);
    CP_COMMIT();

    for (int kc = 0; kc < NCHUNK; kc++){
        if (kc + 1 < NCHUNK){
            issue(kc + 1, (kc + 1) & 1);
            CP_COMMIT();
            CP_WAIT1();
        } else {
            CP_WAIT0();
        }
        __syncthreads();

        uint32_t sb  = sbase + (kc & 1)*STAGE_BYTES;
        uint32_t sAF = sb, sBF = sb + 16384;

        #pragma unroll
        for (int ks = 0; ks < 4; ks++){
            uint32_t koff = ks * 32;
            uint32_t a_off = SMEM_SWIZZLE_128B(a_rowb + a_kb + koff);
            uint32_t b_off = SMEM_SWIZZLE_128B(b_rowb + b_kb + koff);
            uint32_t af[2][4];
            #pragma unroll
            for (int mt = 0; mt < 2; mt++)
                ldsm4(af[mt], sAF + a_off + mt*2048);
            #pragma unroll
            for (int np = 0; np < 4; np++){
                uint32_t bf[4];
                ldsm4(bf, sBF + b_off + np*2048);
                #pragma unroll
                for (int half = 0; half < 2; half++){
                    int nt = np*2 + half;
                    #pragma unroll
                    for (int mt = 0; mt < 2; mt++)
                        mma16816(acc[mt][nt], af[mt], bf + half*2);
                }
            }
        }
        __syncthreads();
    }

    // epilogue: bias + relu
    const float* bias = g_bias3[layer];
    int qrow = lane >> 2;            // 0..7
    int qcol = (lane & 3) * 2;       // 0,2,4,6
    #pragma unroll
    for (int mt = 0; mt < 2; mt++){
        #pragma unroll
        for (int nt = 0; nt < 8; nt++){
            int col  = wn*64 + nt*8 + qcol;
            float2 bb = *(const float2*)&bias[col];
            int r0 = m0 + wm*32 + mt*16 + qrow;
            int r1 = r0 + 8;
            float v00 = fmaxf(acc[mt][nt][0] + bb.x, 0.f);
            float v01 = fmaxf(acc[mt][nt][1] + bb.y, 0.f);
            float v10 = fmaxf(acc[mt][nt][2] + bb.x, 0.f);
            float v11 = fmaxf(acc[mt][nt][3] + bb.y, 0.f);
            if (writeAux){
                if (r0 < NN){
                    __half2 h = __floats2half2_rn(v00, v01);
                    *(__half2*)&g_xh[(size_t)r0*DD + col] = h;
                    *(__half2*)&g_Af[(size_t)r0*KK + 896 + col] = h;
                }
                if (r1 < NN){
                    __half2 h = __floats2half2_rn(v10, v11);
                    *(__half2*)&g_xh[(size_t)r1*DD + col] = h;
                    *(__half2*)&g_Af[(size_t)r1*KK + 896 + col] = h;
                }
            } else {
                if (r0 < NN) *(float2*)&xout[(size_t)r0*DD + col] = make_float2(v00, v01);
                if (r1 < NN) *(float2*)&xout[(size_t)r1*DD + col] = make_float2(v10, v11);
            }
        }
    }
}

// ---------------- graph pooling --------------------------------------------
__global__ void k_zero_out(float* __restrict__ out){
    int i = blockIdx.x*blockDim.x + threadIdx.x;
    if (i < GG*DD) out[i] = 0.f;
}
__device__ __forceinline__ int lowerb(const int* __restrict__ a, int n, int key){
    int lo = 0, hi = n;
    while (lo < hi){
        int mid = (lo + hi) >> 1;
        if (a[mid] < key) lo = mid + 1; else hi = mid;
    }
    return lo;
}
__global__ void k_gsum(const int* __restrict__ n2g, const float* __restrict__ x,
                       float* __restrict__ out){
    int g = blockIdx.x / GSPLIT, c = blockIdx.x % GSPLIT, t = threadIdx.x;
    int lo = lowerb(n2g, NN, g);
    int hi = lowerb(n2g, NN, g+1);
    int len = hi - lo;
    int per = (len + GSPLIT - 1) / GSPLIT;
    int s = lo + c*per;
    int e = min(s + per, hi);
    float acc = 0.f;
    for (int n = s; n < e; n++) acc += x[(size_t)n*DD + t];
    if (e > s) atomicAdd(&out[g*DD + t], acc);
}

// ---------------- launcher --------------------------------------------------
extern "C" void kernel_launch(void* const* d_in, const int* in_sizes, int n_in,
                              void* d_out, int out_size){
    const int*   unit_type   = (const int*)  d_in[0];
    const int*   node_in     = (const int*)  d_in[1];
    const int*   node_out    = (const int*)  d_in[2];
    const int*   relation    = (const int*)  d_in[3];
    const float* edge_weight = (const float*)d_in[4];
    const int*   node2graph  = (const int*)  d_in[5];
    const float* emb         = (const float*)d_in[6];
    const float* W_rel       = (const float*)d_in[7];
    const float* b_rel       = (const float*)d_in[8];
    const float* W_loop      = (const float*)d_in[9];
    const float* b_loop      = (const float*)d_in[10];

    float* out   = (float*)d_out;
    float* x_out = out + GG*DD;

    // idempotent, capture-safe; no static guard (harness rule)
    cudaFuncSetAttribute(k_gemm_mma, cudaFuncAttributeMaxDynamicSharedMemorySize, GEMM_SMEM);

    int nb_ns = (NS + 1023) / 1024;  // 342

    k_embed_zero<<<(NN*32 + 255)/256, 256>>>(unit_type, (const float4*)emb);
    k_hist<<<(EE + 255)/256, 256>>>(node_out, relation);
    k_scan1<<<nb_ns, 1024>>>();
    k_scan23<<<nb_ns, 1024>>>(nb_ns);
    k_scatter<<<(EE + 255)/256, 256>>>(node_in, node_out, relation, edge_weight);

    for (int l = 0; l < NLAYERS; l++){
        k_agg<<<(NS*32 + 255)/256, 256>>>();
        if (l == 0)
            k_prepW<<<(NLAYERS*KK*DD + 255)/256, 256>>>(W_rel, b_rel, W_loop, b_loop);
        if (l < NLAYERS - 1)
            k_gemm_mma<<<MTILES, 256, GEMM_SMEM>>>(nullptr, 1, l);
        else
            k_gemm_mma<<<MTILES, 256, GEMM_SMEM>>>(x_out, 0, l);
    }

    k_zero_out<<<(GG*DD + 255)/256, 256>>>(out);
    k_gsum<<<GG*GSPLIT, 128>>>(node2graph, x_out, out);
}